// round 2
// baseline (speedup 1.0000x reference)
#include <cuda_runtime.h>
#include <cuda_bf16.h>

// Problem constants
#define B_   8
#define L_   2048
#define DM_  512
#define NH_  8
#define DK_  64
#define DV_  64
#define BH_  (B_*NH_)            // 64
#define INV_TEMP 0.125f          // 1/sqrt(64)

// Scratch (device globals; allocation-free kernel_launch)
__device__ float g_Q[BH_ * L_ * DK_];            // 33.5 MB, pre-scaled by 1/TEMP
__device__ float g_K[BH_ * L_ * DK_];            // 33.5 MB
__device__ __nv_bfloat16 g_E[(size_t)BH_ * L_ * L_]; // 536 MB: exp(S) unnormalized
__device__ float g_ell[BH_ * L_];                // row sums of exp(S)
__device__ float g_P[BH_ * L_];                  // pooled = colmean of softmax
__device__ float g_z[B_ * NH_ * DM_];            // z[b,h,m] = sum_k P*x
__device__ float g_res[B_ * DM_];                // sum over L of x (residual*L)

// ---------------------------------------------------------------------------
// Kernel 0: zero the accumulated buffers (graph-capturable, deterministic)
// ---------------------------------------------------------------------------
__global__ void zero_kernel() {
    int i = blockIdx.x * 256 + threadIdx.x;
    if (i < BH_ * L_) { g_ell[i] = 0.f; g_P[i] = 0.f; }
    if (i < B_ * NH_ * DM_) g_z[i] = 0.f;
    if (i < B_ * DM_) g_res[i] = 0.f;
}

// ---------------------------------------------------------------------------
// Kernel 1: Q/K projection. C[16384, 1024] = x[16384,512] @ [w_q;w_k]^T
// 128x128 block tile, 256 threads, 8x8 micro-tile, K-chunk 8.
// ---------------------------------------------------------------------------
__global__ __launch_bounds__(256) void proj_kernel(
    const float* __restrict__ x,
    const float* __restrict__ wq,
    const float* __restrict__ wk)
{
    __shared__ float As[8][132];
    __shared__ float Bs[8][132];
    const int t    = threadIdx.x;
    const int m0   = blockIdx.y << 7;     // row tile over B*L = 16384
    const int n0   = blockIdx.x << 7;     // col tile over 1024 (Q cols 0..511, K cols 512..1023)
    const int lrow = t >> 1;
    const int seg  = (t & 1) << 2;
    const int tx   = t & 15;
    const int ty   = t >> 4;

    const float* arow = x + (size_t)(m0 + lrow) * DM_ + seg;
    const float* wrow;
    {
        int n = n0 + lrow;
        wrow = (n < 512) ? (wq + (size_t)n * DM_ + seg)
                         : (wk + (size_t)(n - 512) * DM_ + seg);
    }

    float acc[8][8] = {};

    for (int kc = 0; kc < DM_ / 8; kc++) {
        float4 av = *(const float4*)(arow + kc * 8);
        float4 bv = *(const float4*)(wrow + kc * 8);
        As[seg + 0][lrow] = av.x; As[seg + 1][lrow] = av.y;
        As[seg + 2][lrow] = av.z; As[seg + 3][lrow] = av.w;
        Bs[seg + 0][lrow] = bv.x; Bs[seg + 1][lrow] = bv.y;
        Bs[seg + 2][lrow] = bv.z; Bs[seg + 3][lrow] = bv.w;
        __syncthreads();
        #pragma unroll
        for (int kk = 0; kk < 8; kk++) {
            float a[8], b[8];
            *(float4*)(a)     = *(const float4*)&As[kk][(ty << 3)];
            *(float4*)(a + 4) = *(const float4*)&As[kk][(ty << 3) + 4];
            *(float4*)(b)     = *(const float4*)&Bs[kk][(tx << 3)];
            *(float4*)(b + 4) = *(const float4*)&Bs[kk][(tx << 3) + 4];
            #pragma unroll
            for (int i = 0; i < 8; i++)
                #pragma unroll
                for (int j = 0; j < 8; j++)
                    acc[i][j] += a[i] * b[j];
        }
        __syncthreads();
    }

    // Epilogue: scatter into g_Q (scaled) / g_K with [b][h][l][d] layout
    #pragma unroll
    for (int i = 0; i < 8; i++) {
        int gm = m0 + (ty << 3) + i;
        int b = gm >> 11, l = gm & 2047;
        #pragma unroll
        for (int j = 0; j < 8; j++) {
            int gn = n0 + (tx << 3) + j;
            if (gn < 512) {
                int h = gn >> 6, d = gn & 63;
                g_Q[(((size_t)(b << 3) + h) * L_ + l) * DK_ + d] = acc[i][j] * INV_TEMP;
            } else {
                int gn2 = gn - 512;
                int h = gn2 >> 6, d = gn2 & 63;
                g_K[(((size_t)(b << 3) + h) * L_ + l) * DK_ + d] = acc[i][j];
            }
        }
    }
}

// ---------------------------------------------------------------------------
// Kernel 2: attention scores. Per (b,h): S = Q_bh @ K_bh^T (Q pre-scaled),
// exp() without max-subtraction (logits O(1), safe), store bf16, row-sum atomics.
// 128x128 tile, depth 64 in chunks of 8.
// ---------------------------------------------------------------------------
__global__ __launch_bounds__(256) void attn_kernel()
{
    __shared__ float As[8][132];
    __shared__ float Bs[8][132];
    const int t  = threadIdx.x;
    const int bh = blockIdx.z;
    const int q0 = blockIdx.y << 7;
    const int k0 = blockIdx.x << 7;
    const int lrow = t >> 1;
    const int seg  = (t & 1) << 2;
    const int tx = t & 15;
    const int ty = t >> 4;

    const float* aptr = g_Q + (size_t)bh * L_ * DK_ + (size_t)(q0 + lrow) * DK_ + seg;
    const float* bptr = g_K + (size_t)bh * L_ * DK_ + (size_t)(k0 + lrow) * DK_ + seg;

    float acc[8][8] = {};

    for (int dc = 0; dc < DK_ / 8; dc++) {
        float4 av = *(const float4*)(aptr + dc * 8);
        float4 bv = *(const float4*)(bptr + dc * 8);
        As[seg + 0][lrow] = av.x; As[seg + 1][lrow] = av.y;
        As[seg + 2][lrow] = av.z; As[seg + 3][lrow] = av.w;
        Bs[seg + 0][lrow] = bv.x; Bs[seg + 1][lrow] = bv.y;
        Bs[seg + 2][lrow] = bv.z; Bs[seg + 3][lrow] = bv.w;
        __syncthreads();
        #pragma unroll
        for (int kk = 0; kk < 8; kk++) {
            float a[8], b[8];
            *(float4*)(a)     = *(const float4*)&As[kk][(ty << 3)];
            *(float4*)(a + 4) = *(const float4*)&As[kk][(ty << 3) + 4];
            *(float4*)(b)     = *(const float4*)&Bs[kk][(tx << 3)];
            *(float4*)(b + 4) = *(const float4*)&Bs[kk][(tx << 3) + 4];
            #pragma unroll
            for (int i = 0; i < 8; i++)
                #pragma unroll
                for (int j = 0; j < 8; j++)
                    acc[i][j] += a[i] * b[j];
        }
        __syncthreads();
    }

    // Epilogue: exp, bf16 pack (16B store), row-sum reduce across 16 tx lanes
    #pragma unroll
    for (int i = 0; i < 8; i++) {
        int q = q0 + (ty << 3) + i;
        float rowsum = 0.f;
        __nv_bfloat162 pr[4];
        #pragma unroll
        for (int jp = 0; jp < 4; jp++) {
            float e0 = __expf(acc[i][2 * jp]);
            float e1 = __expf(acc[i][2 * jp + 1]);
            rowsum += e0 + e1;
            pr[jp] = __floats2bfloat162_rn(e0, e1);
        }
        *reinterpret_cast<uint4*>(
            &g_E[((size_t)(bh * L_ + q)) * L_ + k0 + (tx << 3)]) =
            *reinterpret_cast<uint4*>(pr);
        #pragma unroll
        for (int off = 8; off; off >>= 1)
            rowsum += __shfl_xor_sync(0xffffffffu, rowsum, off);
        if (tx == 0)
            atomicAdd(&g_ell[bh * L_ + q], rowsum);
    }
}

// ---------------------------------------------------------------------------
// Kernel 3: normalized column sums -> pooled P[b,h,k] = (1/L) sum_q expS/ell.
// grid (16 q-chunks, 64 bh). Streaming, partial colsums via atomics.
// ---------------------------------------------------------------------------
__global__ __launch_bounds__(256) void colsum_kernel()
{
    __shared__ float sinv[128];
    const int qc = blockIdx.x;
    const int bh = blockIdx.y;
    const int t  = threadIdx.x;
    if (t < 128)
        sinv[t] = 1.0f / g_ell[bh * L_ + (qc << 7) + t];
    __syncthreads();

    float acc[8] = {};
    const __nv_bfloat16* base =
        g_E + ((size_t)(bh * L_) + (qc << 7)) * L_ + (t << 3);
    #pragma unroll 8
    for (int q = 0; q < 128; q++) {
        uint4 v = *(const uint4*)(base + (size_t)q * L_);
        float r = sinv[q];
        const __nv_bfloat162* pv = reinterpret_cast<const __nv_bfloat162*>(&v);
        #pragma unroll
        for (int p = 0; p < 4; p++) {
            float2 f = __bfloat1622float2(pv[p]);
            acc[2 * p]     += r * f.x;
            acc[2 * p + 1] += r * f.y;
        }
    }
    #pragma unroll
    for (int j = 0; j < 8; j++)
        atomicAdd(&g_P[bh * L_ + (t << 3) + j], acc[j] * (1.0f / (float)L_));
}

// ---------------------------------------------------------------------------
// Kernel 4: z[b,h,m] = sum_l P[b,h,l] * x[b,l,m]; residual raw sums.
// grid (16 l-chunks, 8 batches), 512 threads (one per m-column).
// ---------------------------------------------------------------------------
__global__ __launch_bounds__(512) void zres_kernel(const float* __restrict__ x)
{
    __shared__ float Ps[8][128];
    const int lc = blockIdx.x;
    const int b  = blockIdx.y;
    const int t  = threadIdx.x;
    for (int i = t; i < 1024; i += 512) {
        int h = i >> 7, l = i & 127;
        Ps[h][l] = g_P[((b << 3) + h) * L_ + (lc << 7) + l];
    }
    __syncthreads();

    float zacc[8] = {};
    float racc = 0.f;
    const float* xb = x + ((size_t)b * L_ + (size_t)(lc << 7)) * DM_ + t;
    #pragma unroll 4
    for (int ll = 0; ll < 128; ll++) {
        float xv = xb[(size_t)ll * DM_];
        racc += xv;
        #pragma unroll
        for (int h = 0; h < 8; h++)
            zacc[h] += Ps[h][ll] * xv;
    }
    atomicAdd(&g_res[(b << 9) + t], racc);
    #pragma unroll
    for (int h = 0; h < 8; h++)
        atomicAdd(&g_z[(((b << 3) + h) << 9) + t], zacc[h]);
}

// ---------------------------------------------------------------------------
// Kernel 5: attn_ret, out=z@w_v^T/L, flat@w_fc^T + residual, layernorm.
// grid 8 (batch), 512 threads.
// Output layout: d_out[0 : 4096) = y (8,512); d_out[4096 : 20480) = attn_ret (8,2048)
// ---------------------------------------------------------------------------
__global__ __launch_bounds__(512) void finalize_kernel(
    const float* __restrict__ w_v,
    const float* __restrict__ w_fc,
    const float* __restrict__ gamma,
    const float* __restrict__ beta,
    float* __restrict__ out)
{
    __shared__ float zsh[4096];
    __shared__ float flat[512];
    __shared__ float rs[16], rq[16];
    __shared__ float stats[2];
    const int b = blockIdx.x;
    const int t = threadIdx.x;

    for (int i = t; i < 4096; i += 512)
        zsh[i] = g_z[(size_t)b * 4096 + i];

    // attn_ret[b,k] = mean over heads of pooled
    for (int k = t; k < L_; k += 512) {
        float s = 0.f;
        #pragma unroll
        for (int h = 0; h < 8; h++)
            s += g_P[((b << 3) + h) * L_ + k];
        out[4096 + b * L_ + k] = s * 0.125f;
    }
    __syncthreads();

    // out[b,h,dv] = (1/L) * dot(z[b,h,:], w_v[h*64+dv,:]) -> flat[dv*8+h]
    {
        const int h = t >> 6, dv = t & 63;
        const float4* wv4 = (const float4*)(w_v + (size_t)((h << 6) + dv) * DM_);
        const float4* z4  = (const float4*)(zsh + (h << 9));
        float ov = 0.f;
        #pragma unroll 8
        for (int m = 0; m < DM_ / 4; m++) {
            float4 a = z4[m], w = wv4[m];
            ov += a.x * w.x + a.y * w.y + a.z * w.z + a.w * w.w;
        }
        flat[(dv << 3) + h] = ov * (1.0f / (float)L_);
    }
    __syncthreads();

    // y[b,d] = flat @ w_fc[d,:] + residual
    float acc = g_res[(b << 9) + t] * (1.0f / (float)L_);
    {
        const float4* wf4 = (const float4*)(w_fc + (size_t)t * DM_);
        const float4* f4  = (const float4*)flat;
        #pragma unroll 8
        for (int m = 0; m < DM_ / 4; m++) {
            float4 f = f4[m], w = wf4[m];
            acc += f.x * w.x + f.y * w.y + f.z * w.z + f.w * w.w;
        }
    }

    // layernorm over 512 (biased variance, matching jnp.var)
    float s1 = acc, s2 = acc * acc;
    #pragma unroll
    for (int off = 16; off; off >>= 1) {
        s1 += __shfl_xor_sync(0xffffffffu, s1, off);
        s2 += __shfl_xor_sync(0xffffffffu, s2, off);
    }
    if ((t & 31) == 0) { rs[t >> 5] = s1; rq[t >> 5] = s2; }
    __syncthreads();
    if (t == 0) {
        float S = 0.f, Q2 = 0.f;
        #pragma unroll
        for (int i = 0; i < 16; i++) { S += rs[i]; Q2 += rq[i]; }
        float mu  = S * (1.0f / 512.0f);
        float var = Q2 * (1.0f / 512.0f) - mu * mu;
        stats[0] = mu;
        stats[1] = rsqrtf(var + 1e-6f);
    }
    __syncthreads();
    out[(b << 9) + t] = (acc - stats[0]) * stats[1] * gamma[t] + beta[t];
}

// ---------------------------------------------------------------------------
extern "C" void kernel_launch(void* const* d_in, const int* in_sizes, int n_in,
                              void* d_out, int out_size)
{
    (void)in_sizes; (void)n_in; (void)out_size;
    const float* x     = (const float*)d_in[0];
    const float* w_q   = (const float*)d_in[1];
    const float* w_k   = (const float*)d_in[2];
    const float* w_v   = (const float*)d_in[3];
    const float* w_fc  = (const float*)d_in[4];
    const float* gamma = (const float*)d_in[5];
    const float* beta  = (const float*)d_in[6];
    float* out = (float*)d_out;

    zero_kernel<<<512, 256>>>();
    proj_kernel<<<dim3(8, 128), 256>>>(x, w_q, w_k);
    attn_kernel<<<dim3(16, 16, 64), 256>>>();
    colsum_kernel<<<dim3(16, 64), 256>>>();
    zres_kernel<<<dim3(16, 8), 512>>>(x);
    finalize_kernel<<<8, 512>>>(w_v, w_fc, gamma, beta, out);
}

// round 4
// speedup vs baseline: 2.2882x; 2.2882x over previous
#include <cuda_runtime.h>
#include <cuda_bf16.h>
#include <cstdint>

// Problem constants
#define B_   8
#define L_   2048
#define DM_  512
#define NH_  8
#define DK_  64
#define BH_  (B_*NH_)            // 64
// Q pre-scale: (1/sqrt(DK)) * log2(e), so epilogue is ex2.approx
#define QSCALE 0.18033688011112043f

// Scratch (device globals; allocation-free kernel_launch)
__device__ float g_Q[BH_ * L_ * DK_];            // tf32-rounded, pre-scaled
__device__ float g_K[BH_ * L_ * DK_];            // tf32-rounded
__device__ __nv_bfloat16 g_E[(size_t)BH_ * L_ * L_]; // 536 MB: exp(S) unnormalized
__device__ float g_ell[BH_ * L_];                // row sums of exp(S)
__device__ float g_P[BH_ * L_];                  // pooled = colmean of softmax
__device__ float g_z[B_ * NH_ * DM_];            // z[b,h,m] = sum_k P*x
__device__ float g_res[B_ * DM_];                // sum over L of x (residual*L)

// ---------------------------------------------------------------------------
// Helpers
// ---------------------------------------------------------------------------
__device__ __forceinline__ float to_tf32(float x) {
    uint32_t r;
    asm("cvt.rna.tf32.f32 %0, %1;" : "=r"(r) : "f"(x));   // dst is .b32
    return __uint_as_float(r);
}
__device__ __forceinline__ float fast_exp2(float x) {
    float r;
    asm("ex2.approx.f32 %0, %1;" : "=f"(r) : "f"(x));
    return r;
}
__device__ __forceinline__ void mma_tf32(float c[4],
    uint32_t a0, uint32_t a1, uint32_t a2, uint32_t a3,
    uint32_t b0, uint32_t b1)
{
    asm volatile(
        "mma.sync.aligned.m16n8k8.row.col.f32.tf32.tf32.f32 "
        "{%0,%1,%2,%3}, {%4,%5,%6,%7}, {%8,%9}, {%0,%1,%2,%3};\n"
        : "+f"(c[0]), "+f"(c[1]), "+f"(c[2]), "+f"(c[3])
        : "r"(a0), "r"(a1), "r"(a2), "r"(a3), "r"(b0), "r"(b1));
}

// ---------------------------------------------------------------------------
// Kernel 0: zero accumulated buffers
// ---------------------------------------------------------------------------
__global__ void zero_kernel() {
    int i = blockIdx.x * 256 + threadIdx.x;
    if (i < BH_ * L_) { g_ell[i] = 0.f; g_P[i] = 0.f; }
    if (i < B_ * NH_ * DM_) g_z[i] = 0.f;
    if (i < B_ * DM_) g_res[i] = 0.f;
}

// ---------------------------------------------------------------------------
// Kernel 1: Q/K projection via tf32 mma. C[16384,1024] = x @ [w_q;w_k]^T
// 128x128 tile, 8 warps, warp tile 32x64, k-chunks of 32.
// ---------------------------------------------------------------------------
__global__ __launch_bounds__(256) void proj_kernel(
    const float* __restrict__ x,
    const float* __restrict__ wq,
    const float* __restrict__ wk)
{
    __shared__ float As[128 * 36];
    __shared__ float Bs[128 * 36];
    const int t = threadIdx.x;
    const int m0 = blockIdx.y << 7;
    const int n0 = blockIdx.x << 7;
    const int wid = t >> 5, lane = t & 31;
    const int wm = wid >> 1, wn = wid & 1;
    const int g = lane >> 2, tq = lane & 3;

    float acc[2][8][4] = {};

    for (int kc = 0; kc < 16; kc++) {
        #pragma unroll
        for (int f = t; f < 1024; f += 256) {
            int row = f >> 3, c4 = (f & 7) << 2;
            float4 av = *(const float4*)(x + (size_t)(m0 + row) * DM_ + kc * 32 + c4);
            float* da = &As[row * 36 + c4];
            da[0] = to_tf32(av.x); da[1] = to_tf32(av.y);
            da[2] = to_tf32(av.z); da[3] = to_tf32(av.w);
            int n = n0 + row;
            const float* src = (n < 512) ? (wq + (size_t)n * DM_)
                                         : (wk + (size_t)(n - 512) * DM_);
            float4 bv = *(const float4*)(src + kc * 32 + c4);
            float* db = &Bs[row * 36 + c4];
            db[0] = to_tf32(bv.x); db[1] = to_tf32(bv.y);
            db[2] = to_tf32(bv.z); db[3] = to_tf32(bv.w);
        }
        __syncthreads();
        #pragma unroll
        for (int k0 = 0; k0 < 32; k0 += 8) {
            uint32_t a[2][4], b[8][2];
            #pragma unroll
            for (int i = 0; i < 2; i++) {
                int r = wm * 32 + i * 16 + g;
                a[i][0] = __float_as_uint(As[r * 36 + k0 + tq]);
                a[i][1] = __float_as_uint(As[(r + 8) * 36 + k0 + tq]);
                a[i][2] = __float_as_uint(As[r * 36 + k0 + tq + 4]);
                a[i][3] = __float_as_uint(As[(r + 8) * 36 + k0 + tq + 4]);
            }
            #pragma unroll
            for (int j = 0; j < 8; j++) {
                int n = wn * 64 + j * 8 + g;
                b[j][0] = __float_as_uint(Bs[n * 36 + k0 + tq]);
                b[j][1] = __float_as_uint(Bs[n * 36 + k0 + tq + 4]);
            }
            #pragma unroll
            for (int i = 0; i < 2; i++)
                #pragma unroll
                for (int j = 0; j < 8; j++)
                    mma_tf32(acc[i][j], a[i][0], a[i][1], a[i][2], a[i][3],
                             b[j][0], b[j][1]);
        }
        __syncthreads();
    }

    // Epilogue: scatter tf32-rounded into g_Q (scaled) / g_K, [b][h][l][d]
    #pragma unroll
    for (int i = 0; i < 2; i++) {
        #pragma unroll
        for (int cc = 0; cc < 4; cc++) {
            int r = m0 + wm * 32 + i * 16 + g + ((cc >> 1) << 3);
            int bidx = r >> 11, l = r & 2047;
            #pragma unroll
            for (int j = 0; j < 8; j++) {
                int n = n0 + wn * 64 + j * 8 + 2 * tq + (cc & 1);
                float v = acc[i][j][cc];
                if (n < 512) {
                    int h = n >> 6, d = n & 63;
                    g_Q[(((size_t)(bidx << 3) + h) * L_ + l) * DK_ + d] =
                        to_tf32(v * QSCALE);
                } else {
                    int n2 = n - 512;
                    int h = n2 >> 6, d = n2 & 63;
                    g_K[(((size_t)(bidx << 3) + h) * L_ + l) * DK_ + d] = to_tf32(v);
                }
            }
        }
    }
}

// ---------------------------------------------------------------------------
// Kernel 2: attention scores via tf32 mma. S = Q @ K^T (Q pre-scaled by
// log2e/8), E = 2^S stored bf16, row sums via quad-shuffle + atomics.
// 128x128 tile, full depth 64 staged once in dynamic smem (69.6 KB).
// ---------------------------------------------------------------------------
__global__ __launch_bounds__(256) void attn_kernel()
{
    extern __shared__ float sh[];
    float* Qs = sh;                 // [128][68]
    float* Ks = sh + 128 * 68;      // [128][68]
    const int t = threadIdx.x;
    const int bh = blockIdx.z;
    const int q0 = blockIdx.y << 7;
    const int k0b = blockIdx.x << 7;
    const int wid = t >> 5, lane = t & 31;
    const int wm = wid >> 1, wn = wid & 1;
    const int g = lane >> 2, tq = lane & 3;

    const float* qsrc = g_Q + (size_t)bh * L_ * DK_ + (size_t)q0 * DK_;
    const float* ksrc = g_K + (size_t)bh * L_ * DK_ + (size_t)k0b * DK_;
    #pragma unroll
    for (int f = t; f < 2048; f += 256) {
        int row = f >> 4, c4 = (f & 15) << 2;
        *(float4*)&Qs[row * 68 + c4] = *(const float4*)(qsrc + row * 64 + c4);
        *(float4*)&Ks[row * 68 + c4] = *(const float4*)(ksrc + row * 64 + c4);
    }
    __syncthreads();

    float acc[2][8][4] = {};
    #pragma unroll
    for (int k0 = 0; k0 < 64; k0 += 8) {
        uint32_t a[2][4], b[8][2];
        #pragma unroll
        for (int i = 0; i < 2; i++) {
            int r = wm * 32 + i * 16 + g;
            a[i][0] = __float_as_uint(Qs[r * 68 + k0 + tq]);
            a[i][1] = __float_as_uint(Qs[(r + 8) * 68 + k0 + tq]);
            a[i][2] = __float_as_uint(Qs[r * 68 + k0 + tq + 4]);
            a[i][3] = __float_as_uint(Qs[(r + 8) * 68 + k0 + tq + 4]);
        }
        #pragma unroll
        for (int j = 0; j < 8; j++) {
            int n = wn * 64 + j * 8 + g;
            b[j][0] = __float_as_uint(Ks[n * 68 + k0 + tq]);
            b[j][1] = __float_as_uint(Ks[n * 68 + k0 + tq + 4]);
        }
        #pragma unroll
        for (int i = 0; i < 2; i++)
            #pragma unroll
            for (int j = 0; j < 8; j++)
                mma_tf32(acc[i][j], a[i][0], a[i][1], a[i][2], a[i][3],
                         b[j][0], b[j][1]);
    }

    // Epilogue: 2^s, bf16x2 stores, row sums (quad reduce -> atomics)
    #pragma unroll
    for (int i = 0; i < 2; i++) {
        int r0 = q0 + wm * 32 + i * 16 + g;
        int r1 = r0 + 8;
        float s0 = 0.f, s1 = 0.f;
        #pragma unroll
        for (int j = 0; j < 8; j++) {
            float e0 = fast_exp2(acc[i][j][0]);
            float e1 = fast_exp2(acc[i][j][1]);
            float e2 = fast_exp2(acc[i][j][2]);
            float e3 = fast_exp2(acc[i][j][3]);
            s0 += e0 + e1; s1 += e2 + e3;
            int col = k0b + wn * 64 + j * 8 + 2 * tq;
            *(__nv_bfloat162*)&g_E[((size_t)(bh * L_ + r0)) * L_ + col] =
                __floats2bfloat162_rn(e0, e1);
            *(__nv_bfloat162*)&g_E[((size_t)(bh * L_ + r1)) * L_ + col] =
                __floats2bfloat162_rn(e2, e3);
        }
        s0 += __shfl_xor_sync(0xffffffffu, s0, 1);
        s0 += __shfl_xor_sync(0xffffffffu, s0, 2);
        s1 += __shfl_xor_sync(0xffffffffu, s1, 1);
        s1 += __shfl_xor_sync(0xffffffffu, s1, 2);
        if (tq == 0) {
            atomicAdd(&g_ell[bh * L_ + r0], s0);
            atomicAdd(&g_ell[bh * L_ + r1], s1);
        }
    }
}

// ---------------------------------------------------------------------------
// Kernel 3: pooled P[b,h,k] = (1/L) sum_q E/ell  (at HBM roofline; unchanged)
// ---------------------------------------------------------------------------
__global__ __launch_bounds__(256) void colsum_kernel()
{
    __shared__ float sinv[128];
    const int qc = blockIdx.x;
    const int bh = blockIdx.y;
    const int t  = threadIdx.x;
    if (t < 128)
        sinv[t] = 1.0f / g_ell[bh * L_ + (qc << 7) + t];
    __syncthreads();

    float acc[8] = {};
    const __nv_bfloat16* base =
        g_E + ((size_t)(bh * L_) + (qc << 7)) * L_ + (t << 3);
    #pragma unroll 8
    for (int q = 0; q < 128; q++) {
        uint4 v = *(const uint4*)(base + (size_t)q * L_);
        float r = sinv[q];
        const __nv_bfloat162* pv = reinterpret_cast<const __nv_bfloat162*>(&v);
        #pragma unroll
        for (int p = 0; p < 4; p++) {
            float2 f = __bfloat1622float2(pv[p]);
            acc[2 * p]     += r * f.x;
            acc[2 * p + 1] += r * f.y;
        }
    }
    #pragma unroll
    for (int j = 0; j < 8; j++)
        atomicAdd(&g_P[bh * L_ + (t << 3) + j], acc[j] * (1.0f / (float)L_));
}

// ---------------------------------------------------------------------------
// Kernel 4: z[b,h,m] = sum_l P[b,h,l]*x[b,l,m]; residual sums
// ---------------------------------------------------------------------------
__global__ __launch_bounds__(512) void zres_kernel(const float* __restrict__ x)
{
    __shared__ float Ps[8][128];
    const int lc = blockIdx.x;
    const int b  = blockIdx.y;
    const int t  = threadIdx.x;
    for (int i = t; i < 1024; i += 512) {
        int h = i >> 7, l = i & 127;
        Ps[h][l] = g_P[((b << 3) + h) * L_ + (lc << 7) + l];
    }
    __syncthreads();

    float zacc[8] = {};
    float racc = 0.f;
    const float* xb = x + ((size_t)b * L_ + (size_t)(lc << 7)) * DM_ + t;
    #pragma unroll 4
    for (int ll = 0; ll < 128; ll++) {
        float xv = xb[(size_t)ll * DM_];
        racc += xv;
        #pragma unroll
        for (int h = 0; h < 8; h++)
            zacc[h] += Ps[h][ll] * xv;
    }
    atomicAdd(&g_res[(b << 9) + t], racc);
    #pragma unroll
    for (int h = 0; h < 8; h++)
        atomicAdd(&g_z[(((b << 3) + h) << 9) + t], zacc[h]);
}

// ---------------------------------------------------------------------------
// Kernel 5: attn_ret, out = z@w_v^T/L, flat@w_fc^T + residual, layernorm
// ---------------------------------------------------------------------------
__global__ __launch_bounds__(512) void finalize_kernel(
    const float* __restrict__ w_v,
    const float* __restrict__ w_fc,
    const float* __restrict__ gamma,
    const float* __restrict__ beta,
    float* __restrict__ out)
{
    __shared__ float zsh[4096];
    __shared__ float flat[512];
    __shared__ float rs[16], rq[16];
    __shared__ float stats[2];
    const int b = blockIdx.x;
    const int t = threadIdx.x;

    for (int i = t; i < 4096; i += 512)
        zsh[i] = g_z[(size_t)b * 4096 + i];

    for (int k = t; k < L_; k += 512) {
        float s = 0.f;
        #pragma unroll
        for (int h = 0; h < 8; h++)
            s += g_P[((b << 3) + h) * L_ + k];
        out[4096 + b * L_ + k] = s * 0.125f;
    }
    __syncthreads();

    {
        const int h = t >> 6, dv = t & 63;
        const float4* wv4 = (const float4*)(w_v + (size_t)((h << 6) + dv) * DM_);
        const float4* z4  = (const float4*)(zsh + (h << 9));
        float ov = 0.f;
        #pragma unroll 8
        for (int m = 0; m < DM_ / 4; m++) {
            float4 a = z4[m], w = wv4[m];
            ov += a.x * w.x + a.y * w.y + a.z * w.z + a.w * w.w;
        }
        flat[(dv << 3) + h] = ov * (1.0f / (float)L_);
    }
    __syncthreads();

    float acc = g_res[(b << 9) + t] * (1.0f / (float)L_);
    {
        const float4* wf4 = (const float4*)(w_fc + (size_t)t * DM_);
        const float4* f4  = (const float4*)flat;
        #pragma unroll 8
        for (int m = 0; m < DM_ / 4; m++) {
            float4 f = f4[m], w = wf4[m];
            acc += f.x * w.x + f.y * w.y + f.z * w.z + f.w * w.w;
        }
    }

    float s1 = acc, s2 = acc * acc;
    #pragma unroll
    for (int off = 16; off; off >>= 1) {
        s1 += __shfl_xor_sync(0xffffffffu, s1, off);
        s2 += __shfl_xor_sync(0xffffffffu, s2, off);
    }
    if ((t & 31) == 0) { rs[t >> 5] = s1; rq[t >> 5] = s2; }
    __syncthreads();
    if (t == 0) {
        float S = 0.f, Q2 = 0.f;
        #pragma unroll
        for (int i = 0; i < 16; i++) { S += rs[i]; Q2 += rq[i]; }
        float mu  = S * (1.0f / 512.0f);
        float var = Q2 * (1.0f / 512.0f) - mu * mu;
        stats[0] = mu;
        stats[1] = rsqrtf(var + 1e-6f);
    }
    __syncthreads();
    out[(b << 9) + t] = (acc - stats[0]) * stats[1] * gamma[t] + beta[t];
}

// ---------------------------------------------------------------------------
extern "C" void kernel_launch(void* const* d_in, const int* in_sizes, int n_in,
                              void* d_out, int out_size)
{
    (void)in_sizes; (void)n_in; (void)out_size;
    const float* x     = (const float*)d_in[0];
    const float* w_q   = (const float*)d_in[1];
    const float* w_k   = (const float*)d_in[2];
    const float* w_v   = (const float*)d_in[3];
    const float* w_fc  = (const float*)d_in[4];
    const float* gamma = (const float*)d_in[5];
    const float* beta  = (const float*)d_in[6];
    float* out = (float*)d_out;

    const int attn_smem = 2 * 128 * 68 * (int)sizeof(float);  // 69632 B
    cudaFuncSetAttribute(attn_kernel,
                         cudaFuncAttributeMaxDynamicSharedMemorySize, attn_smem);

    zero_kernel<<<512, 256>>>();
    proj_kernel<<<dim3(8, 128), 256>>>(x, w_q, w_k);
    attn_kernel<<<dim3(16, 16, 64), 256, attn_smem>>>();
    colsum_kernel<<<dim3(16, 64), 256>>>();
    zres_kernel<<<dim3(16, 8), 512>>>(x);
    finalize_kernel<<<8, 512>>>(w_v, w_fc, gamma, beta, out);
}

// round 5
// speedup vs baseline: 2.5338x; 1.1073x over previous
#include <cuda_runtime.h>
#include <cuda_bf16.h>
#include <cstdint>

// Problem constants
#define B_   8
#define L_   2048
#define DM_  512
#define NH_  8
#define DK_  64
#define BH_  (B_*NH_)            // 64
// Q pre-scale: (1/sqrt(DK)) * log2(e), so epilogue is ex2.approx
#define QSCALE 0.18033688011112043f

// Scratch (device globals; allocation-free kernel_launch)
__device__ __nv_bfloat16 g_Qh[BH_ * L_ * DK_];   // bf16, pre-scaled by QSCALE
__device__ __nv_bfloat16 g_Kh[BH_ * L_ * DK_];   // bf16
__device__ float g_ell[BH_ * L_];                // row sums of exp2(S)
__device__ float g_P[BH_ * L_];                  // pooled = colmean of softmax
__device__ float g_z[B_ * NH_ * DM_];            // z[b,h,m] = sum_k P*x
__device__ float g_res[B_ * DM_];                // sum over L of x (residual*L)

// ---------------------------------------------------------------------------
// Helpers
// ---------------------------------------------------------------------------
__device__ __forceinline__ float to_tf32(float x) {
    uint32_t r;
    asm("cvt.rna.tf32.f32 %0, %1;" : "=r"(r) : "f"(x));
    return __uint_as_float(r);
}
__device__ __forceinline__ float fast_exp2(float x) {
    float r;
    asm("ex2.approx.f32 %0, %1;" : "=f"(r) : "f"(x));
    return r;
}
__device__ __forceinline__ void mma_tf32(float c[4],
    uint32_t a0, uint32_t a1, uint32_t a2, uint32_t a3,
    uint32_t b0, uint32_t b1)
{
    asm volatile(
        "mma.sync.aligned.m16n8k8.row.col.f32.tf32.tf32.f32 "
        "{%0,%1,%2,%3}, {%4,%5,%6,%7}, {%8,%9}, {%0,%1,%2,%3};\n"
        : "+f"(c[0]), "+f"(c[1]), "+f"(c[2]), "+f"(c[3])
        : "r"(a0), "r"(a1), "r"(a2), "r"(a3), "r"(b0), "r"(b1));
}
__device__ __forceinline__ void mma_bf16(float c[4],
    uint32_t a0, uint32_t a1, uint32_t a2, uint32_t a3,
    uint32_t b0, uint32_t b1)
{
    asm volatile(
        "mma.sync.aligned.m16n8k16.row.col.f32.bf16.bf16.f32 "
        "{%0,%1,%2,%3}, {%4,%5,%6,%7}, {%8,%9}, {%0,%1,%2,%3};\n"
        : "+f"(c[0]), "+f"(c[1]), "+f"(c[2]), "+f"(c[3])
        : "r"(a0), "r"(a1), "r"(a2), "r"(a3), "r"(b0), "r"(b1));
}

// ---------------------------------------------------------------------------
// Kernel 0: zero accumulated buffers
// ---------------------------------------------------------------------------
__global__ void zero_kernel() {
    int i = blockIdx.x * 256 + threadIdx.x;
    if (i < BH_ * L_) { g_ell[i] = 0.f; g_P[i] = 0.f; }
    if (i < B_ * NH_ * DM_) g_z[i] = 0.f;
    if (i < B_ * DM_) g_res[i] = 0.f;
}

// ---------------------------------------------------------------------------
// Kernel 1: Q/K projection via tf32 mma; outputs bf16 (Q pre-scaled).
// 128x128 tile, 8 warps, warp tile 32x64, k-chunks of 32.
// ---------------------------------------------------------------------------
__global__ __launch_bounds__(256) void proj_kernel(
    const float* __restrict__ x,
    const float* __restrict__ wq,
    const float* __restrict__ wk)
{
    __shared__ float As[128 * 36];
    __shared__ float Bs[128 * 36];
    const int t = threadIdx.x;
    const int m0 = blockIdx.y << 7;
    const int n0 = blockIdx.x << 7;
    const int wid = t >> 5, lane = t & 31;
    const int wm = wid >> 1, wn = wid & 1;
    const int g = lane >> 2, tq = lane & 3;

    float acc[2][8][4] = {};

    for (int kc = 0; kc < 16; kc++) {
        #pragma unroll
        for (int f = t; f < 1024; f += 256) {
            int row = f >> 3, c4 = (f & 7) << 2;
            float4 av = *(const float4*)(x + (size_t)(m0 + row) * DM_ + kc * 32 + c4);
            float* da = &As[row * 36 + c4];
            da[0] = to_tf32(av.x); da[1] = to_tf32(av.y);
            da[2] = to_tf32(av.z); da[3] = to_tf32(av.w);
            int n = n0 + row;
            const float* src = (n < 512) ? (wq + (size_t)n * DM_)
                                         : (wk + (size_t)(n - 512) * DM_);
            float4 bv = *(const float4*)(src + kc * 32 + c4);
            float* db = &Bs[row * 36 + c4];
            db[0] = to_tf32(bv.x); db[1] = to_tf32(bv.y);
            db[2] = to_tf32(bv.z); db[3] = to_tf32(bv.w);
        }
        __syncthreads();
        #pragma unroll
        for (int k0 = 0; k0 < 32; k0 += 8) {
            uint32_t a[2][4], b[8][2];
            #pragma unroll
            for (int i = 0; i < 2; i++) {
                int r = wm * 32 + i * 16 + g;
                a[i][0] = __float_as_uint(As[r * 36 + k0 + tq]);
                a[i][1] = __float_as_uint(As[(r + 8) * 36 + k0 + tq]);
                a[i][2] = __float_as_uint(As[r * 36 + k0 + tq + 4]);
                a[i][3] = __float_as_uint(As[(r + 8) * 36 + k0 + tq + 4]);
            }
            #pragma unroll
            for (int j = 0; j < 8; j++) {
                int n = wn * 64 + j * 8 + g;
                b[j][0] = __float_as_uint(Bs[n * 36 + k0 + tq]);
                b[j][1] = __float_as_uint(Bs[n * 36 + k0 + tq + 4]);
            }
            #pragma unroll
            for (int i = 0; i < 2; i++)
                #pragma unroll
                for (int j = 0; j < 8; j++)
                    mma_tf32(acc[i][j], a[i][0], a[i][1], a[i][2], a[i][3],
                             b[j][0], b[j][1]);
        }
        __syncthreads();
    }

    // Epilogue: bf16x2 stores into g_Qh (scaled) / g_Kh, [b][h][l][d]
    #pragma unroll
    for (int i = 0; i < 2; i++) {
        #pragma unroll
        for (int rr = 0; rr < 2; rr++) {
            int r = m0 + wm * 32 + i * 16 + g + rr * 8;
            int bidx = r >> 11, l = r & 2047;
            #pragma unroll
            for (int j = 0; j < 8; j++) {
                int n = n0 + wn * 64 + j * 8 + 2 * tq;
                float v0 = acc[i][j][rr * 2 + 0];
                float v1 = acc[i][j][rr * 2 + 1];
                if (n < 512) {
                    int h = n >> 6, d = n & 63;
                    *(__nv_bfloat162*)&g_Qh[(((size_t)(bidx << 3) + h) * L_ + l) * DK_ + d] =
                        __floats2bfloat162_rn(v0 * QSCALE, v1 * QSCALE);
                } else {
                    int n2 = n - 512;
                    int h = n2 >> 6, d = n2 & 63;
                    *(__nv_bfloat162*)&g_Kh[(((size_t)(bidx << 3) + h) * L_ + l) * DK_ + d] =
                        __floats2bfloat162_rn(v0, v1);
                }
            }
        }
    }
}

// ---------------------------------------------------------------------------
// Shared attention tile core (bf16 m16n8k16): computes 128x128 S-tile accs.
// smem word stride 36 (bf16x2 words), conflict-free fragment loads.
// ---------------------------------------------------------------------------
__device__ __forceinline__ void attn_tile_mma(
    const uint32_t* sQ, const uint32_t* sK,
    int wm, int wn, int g, int tq, float acc[2][8][4])
{
    #pragma unroll
    for (int k0w = 0; k0w < 32; k0w += 8) {   // 4 k16 steps (word offsets)
        uint32_t a[2][4], b[8][2];
        #pragma unroll
        for (int i = 0; i < 2; i++) {
            int r = wm * 32 + i * 16 + g;
            a[i][0] = sQ[r * 36 + k0w + tq];
            a[i][1] = sQ[(r + 8) * 36 + k0w + tq];
            a[i][2] = sQ[r * 36 + k0w + 4 + tq];
            a[i][3] = sQ[(r + 8) * 36 + k0w + 4 + tq];
        }
        #pragma unroll
        for (int j = 0; j < 8; j++) {
            int n = wn * 64 + j * 8 + g;
            b[j][0] = sK[n * 36 + k0w + tq];
            b[j][1] = sK[n * 36 + k0w + 4 + tq];
        }
        #pragma unroll
        for (int i = 0; i < 2; i++)
            #pragma unroll
            for (int j = 0; j < 8; j++)
                mma_bf16(acc[i][j], a[i][0], a[i][1], a[i][2], a[i][3],
                         b[j][0], b[j][1]);
    }
}

__device__ __forceinline__ void attn_load_tiles(
    uint32_t* sQ, uint32_t* sK, int bh, int q0, int k0b, int t)
{
    const uint32_t* qsrc =
        (const uint32_t*)(g_Qh + (size_t)bh * L_ * DK_ + (size_t)q0 * DK_);
    const uint32_t* ksrc =
        (const uint32_t*)(g_Kh + (size_t)bh * L_ * DK_ + (size_t)k0b * DK_);
    #pragma unroll
    for (int f = t; f < 1024; f += 256) {
        int row = f >> 3, w4 = (f & 7) << 2;   // 32 words/row, 8 uint4
        *(uint4*)&sQ[row * 36 + w4] = *(const uint4*)(qsrc + row * 32 + w4);
        *(uint4*)&sK[row * 36 + w4] = *(const uint4*)(ksrc + row * 32 + w4);
    }
}

// ---------------------------------------------------------------------------
// Kernel 2a: pass 1 — row sums of exp2(S) into g_ell (atomics).
// ---------------------------------------------------------------------------
__global__ __launch_bounds__(256) void attn_rowsum_kernel()
{
    __shared__ uint32_t sQ[128 * 36];
    __shared__ uint32_t sK[128 * 36];
    const int t = threadIdx.x;
    const int bh = blockIdx.z;
    const int q0 = blockIdx.y << 7;
    const int k0b = blockIdx.x << 7;
    const int wid = t >> 5, lane = t & 31;
    const int wm = wid >> 1, wn = wid & 1;
    const int g = lane >> 2, tq = lane & 3;

    attn_load_tiles(sQ, sK, bh, q0, k0b, t);
    __syncthreads();

    float acc[2][8][4] = {};
    attn_tile_mma(sQ, sK, wm, wn, g, tq, acc);

    #pragma unroll
    for (int i = 0; i < 2; i++) {
        int r0 = q0 + wm * 32 + i * 16 + g;
        int r1 = r0 + 8;
        float s0 = 0.f, s1 = 0.f;
        #pragma unroll
        for (int j = 0; j < 8; j++) {
            s0 += fast_exp2(acc[i][j][0]) + fast_exp2(acc[i][j][1]);
            s1 += fast_exp2(acc[i][j][2]) + fast_exp2(acc[i][j][3]);
        }
        s0 += __shfl_xor_sync(0xffffffffu, s0, 1);
        s0 += __shfl_xor_sync(0xffffffffu, s0, 2);
        s1 += __shfl_xor_sync(0xffffffffu, s1, 1);
        s1 += __shfl_xor_sync(0xffffffffu, s1, 2);
        if (tq == 0) {
            atomicAdd(&g_ell[bh * L_ + r0], s0);
            atomicAdd(&g_ell[bh * L_ + r1], s1);
        }
    }
}

// ---------------------------------------------------------------------------
// Kernel 2b: pass 2 — recompute S, scale rows by 1/ell, column sums -> g_P.
// ---------------------------------------------------------------------------
__global__ __launch_bounds__(256) void attn_colsum_kernel()
{
    __shared__ uint32_t sQ[128 * 36];
    __shared__ uint32_t sK[128 * 36];
    __shared__ float colsum[128];
    const int t = threadIdx.x;
    const int bh = blockIdx.z;
    const int q0 = blockIdx.y << 7;
    const int k0b = blockIdx.x << 7;
    const int wid = t >> 5, lane = t & 31;
    const int wm = wid >> 1, wn = wid & 1;
    const int g = lane >> 2, tq = lane & 3;

    attn_load_tiles(sQ, sK, bh, q0, k0b, t);
    if (t < 128) colsum[t] = 0.f;
    __syncthreads();

    float acc[2][8][4] = {};
    attn_tile_mma(sQ, sK, wm, wn, g, tq, acc);

    // per-row 1/ell (4 distinct rows per thread)
    float inv[2][2];
    #pragma unroll
    for (int i = 0; i < 2; i++) {
        int r0 = q0 + wm * 32 + i * 16 + g;
        inv[i][0] = 1.0f / g_ell[bh * L_ + r0];
        inv[i][1] = 1.0f / g_ell[bh * L_ + r0 + 8];
    }

    // per-thread partial column sums (16 cols: j*8 + 2tq + {0,1})
    float cs[16];
    #pragma unroll
    for (int c = 0; c < 16; c++) cs[c] = 0.f;
    #pragma unroll
    for (int i = 0; i < 2; i++) {
        #pragma unroll
        for (int j = 0; j < 8; j++) {
            float e0 = fast_exp2(acc[i][j][0]);
            float e1 = fast_exp2(acc[i][j][1]);
            float e2 = fast_exp2(acc[i][j][2]);
            float e3 = fast_exp2(acc[i][j][3]);
            cs[2 * j]     += e0 * inv[i][0] + e2 * inv[i][1];
            cs[2 * j + 1] += e1 * inv[i][0] + e3 * inv[i][1];
        }
    }
    // reduce over the 8 g-lanes (lane bits 2,3,4)
    #pragma unroll
    for (int off = 4; off <= 16; off <<= 1)
        #pragma unroll
        for (int c = 0; c < 16; c++)
            cs[c] += __shfl_xor_sync(0xffffffffu, cs[c], off);

    if (lane < 4) {   // g == 0, tq == lane
        #pragma unroll
        for (int j = 0; j < 8; j++) {
            atomicAdd(&colsum[wn * 64 + j * 8 + 2 * tq],     cs[2 * j]);
            atomicAdd(&colsum[wn * 64 + j * 8 + 2 * tq + 1], cs[2 * j + 1]);
        }
    }
    __syncthreads();
    if (t < 128)
        atomicAdd(&g_P[bh * L_ + k0b + t], colsum[t] * (1.0f / (float)L_));
}

// ---------------------------------------------------------------------------
// Kernel 4: z[b,h,m] = sum_l P[b,h,l]*x[b,l,m]; residual sums
// ---------------------------------------------------------------------------
__global__ __launch_bounds__(512) void zres_kernel(const float* __restrict__ x)
{
    __shared__ float Ps[8][128];
    const int lc = blockIdx.x;
    const int b  = blockIdx.y;
    const int t  = threadIdx.x;
    for (int i = t; i < 1024; i += 512) {
        int h = i >> 7, l = i & 127;
        Ps[h][l] = g_P[((b << 3) + h) * L_ + (lc << 7) + l];
    }
    __syncthreads();

    float zacc[8] = {};
    float racc = 0.f;
    const float* xb = x + ((size_t)b * L_ + (size_t)(lc << 7)) * DM_ + t;
    #pragma unroll 4
    for (int ll = 0; ll < 128; ll++) {
        float xv = xb[(size_t)ll * DM_];
        racc += xv;
        #pragma unroll
        for (int h = 0; h < 8; h++)
            zacc[h] += Ps[h][ll] * xv;
    }
    atomicAdd(&g_res[(b << 9) + t], racc);
    #pragma unroll
    for (int h = 0; h < 8; h++)
        atomicAdd(&g_z[(((b << 3) + h) << 9) + t], zacc[h]);
}

// ---------------------------------------------------------------------------
// Kernel 5: attn_ret, out = z@w_v^T/L, flat@w_fc^T + residual, layernorm
// ---------------------------------------------------------------------------
__global__ __launch_bounds__(512) void finalize_kernel(
    const float* __restrict__ w_v,
    const float* __restrict__ w_fc,
    const float* __restrict__ gamma,
    const float* __restrict__ beta,
    float* __restrict__ out)
{
    __shared__ float zsh[4096];
    __shared__ float flat[512];
    __shared__ float rs[16], rq[16];
    __shared__ float stats[2];
    const int b = blockIdx.x;
    const int t = threadIdx.x;

    for (int i = t; i < 4096; i += 512)
        zsh[i] = g_z[(size_t)b * 4096 + i];

    for (int k = t; k < L_; k += 512) {
        float s = 0.f;
        #pragma unroll
        for (int h = 0; h < 8; h++)
            s += g_P[((b << 3) + h) * L_ + k];
        out[4096 + b * L_ + k] = s * 0.125f;
    }
    __syncthreads();

    {
        const int h = t >> 6, dv = t & 63;
        const float4* wv4 = (const float4*)(w_v + (size_t)((h << 6) + dv) * DM_);
        const float4* z4  = (const float4*)(zsh + (h << 9));
        float ov = 0.f;
        #pragma unroll 8
        for (int m = 0; m < DM_ / 4; m++) {
            float4 a = z4[m], w = wv4[m];
            ov += a.x * w.x + a.y * w.y + a.z * w.z + a.w * w.w;
        }
        flat[(dv << 3) + h] = ov * (1.0f / (float)L_);
    }
    __syncthreads();

    float acc = g_res[(b << 9) + t] * (1.0f / (float)L_);
    {
        const float4* wf4 = (const float4*)(w_fc + (size_t)t * DM_);
        const float4* f4  = (const float4*)flat;
        #pragma unroll 8
        for (int m = 0; m < DM_ / 4; m++) {
            float4 f = f4[m], w = wf4[m];
            acc += f.x * w.x + f.y * w.y + f.z * w.z + f.w * w.w;
        }
    }

    float s1 = acc, s2 = acc * acc;
    #pragma unroll
    for (int off = 16; off; off >>= 1) {
        s1 += __shfl_xor_sync(0xffffffffu, s1, off);
        s2 += __shfl_xor_sync(0xffffffffu, s2, off);
    }
    if ((t & 31) == 0) { rs[t >> 5] = s1; rq[t >> 5] = s2; }
    __syncthreads();
    if (t == 0) {
        float S = 0.f, Q2 = 0.f;
        #pragma unroll
        for (int i = 0; i < 16; i++) { S += rs[i]; Q2 += rq[i]; }
        float mu  = S * (1.0f / 512.0f);
        float var = Q2 * (1.0f / 512.0f) - mu * mu;
        stats[0] = mu;
        stats[1] = rsqrtf(var + 1e-6f);
    }
    __syncthreads();
    out[(b << 9) + t] = (acc - stats[0]) * stats[1] * gamma[t] + beta[t];
}

// ---------------------------------------------------------------------------
extern "C" void kernel_launch(void* const* d_in, const int* in_sizes, int n_in,
                              void* d_out, int out_size)
{
    (void)in_sizes; (void)n_in; (void)out_size;
    const float* x     = (const float*)d_in[0];
    const float* w_q   = (const float*)d_in[1];
    const float* w_k   = (const float*)d_in[2];
    const float* w_v   = (const float*)d_in[3];
    const float* w_fc  = (const float*)d_in[4];
    const float* gamma = (const float*)d_in[5];
    const float* beta  = (const float*)d_in[6];
    float* out = (float*)d_out;

    zero_kernel<<<512, 256>>>();
    proj_kernel<<<dim3(8, 128), 256>>>(x, w_q, w_k);
    attn_rowsum_kernel<<<dim3(16, 16, 64), 256>>>();
    attn_colsum_kernel<<<dim3(16, 16, 64), 256>>>();
    zres_kernel<<<dim3(16, 8), 512>>>(x);
    finalize_kernel<<<8, 512>>>(w_v, w_fc, gamma, beta, out);
}

// round 7
// speedup vs baseline: 2.6885x; 1.0611x over previous
#include <cuda_runtime.h>
#include <cuda_bf16.h>
#include <cstdint>

// Problem constants
#define B_   8
#define L_   2048
#define DM_  512
#define NH_  8
#define DK_  64
#define BH_  (B_*NH_)            // 64
// Q pre-scale: (1/sqrt(DK)) * log2(e), so epilogue is ex2.approx
#define QSCALE 0.18033688011112043f

// Scratch (device globals; allocation-free kernel_launch)
__device__ __nv_bfloat16 g_Qh[BH_ * L_ * DK_];   // bf16, pre-scaled by QSCALE
__device__ __nv_bfloat16 g_Kh[BH_ * L_ * DK_];   // bf16
__device__ float g_ell[BH_ * L_];                // row sums of exp2(S)
__device__ float g_P[BH_ * L_];                  // pooled = colmean of softmax
__device__ float g_z[B_ * NH_ * DM_];            // z[b,h,m] = sum_k P*x
__device__ float g_res[B_ * DM_];                // sum over L of x (residual*L)

// ---------------------------------------------------------------------------
// Helpers
// ---------------------------------------------------------------------------
__device__ __forceinline__ float fast_exp2(float x) {
    float r;
    asm("ex2.approx.f32 %0, %1;" : "=f"(r) : "f"(x));
    return r;
}
// pack two floats to bf16x2 word (lo = first arg in low half)
__device__ __forceinline__ uint32_t pack_bf162(float lo, float hi) {
    uint32_t r;
    asm("cvt.rn.bf16x2.f32 %0, %1, %2;" : "=r"(r) : "f"(hi), "f"(lo));
    return r;
}
__device__ __forceinline__ void mma_bf16(float c[4],
    uint32_t a0, uint32_t a1, uint32_t a2, uint32_t a3,
    uint32_t b0, uint32_t b1)
{
    asm volatile(
        "mma.sync.aligned.m16n8k16.row.col.f32.bf16.bf16.f32 "
        "{%0,%1,%2,%3}, {%4,%5,%6,%7}, {%8,%9}, {%0,%1,%2,%3};\n"
        : "+f"(c[0]), "+f"(c[1]), "+f"(c[2]), "+f"(c[3])
        : "r"(a0), "r"(a1), "r"(a2), "r"(a3), "r"(b0), "r"(b1));
}
__device__ __forceinline__ void ldsm_x4(uint32_t& r0, uint32_t& r1,
                                        uint32_t& r2, uint32_t& r3,
                                        uint32_t addr)
{
    asm volatile("ldmatrix.sync.aligned.m8n8.x4.shared.b16 {%0,%1,%2,%3}, [%4];"
                 : "=r"(r0), "=r"(r1), "=r"(r2), "=r"(r3) : "r"(addr));
}
__device__ __forceinline__ uint32_t smem_u32(const void* p) {
    return (uint32_t)__cvta_generic_to_shared(p);
}

// ---------------------------------------------------------------------------
// Shared bf16 MMA tile core: 128x128 output tile per 256-thread block,
// 8 warps with 32x64 warp tiles, depth 64 (4 k16 steps). Fragments via
// ldmatrix.x4; smem rows 64 bf16 = 32 words, stride 36 words (LDSM
// conflict-free: row offsets mod 32 banks = 4r).
// ---------------------------------------------------------------------------
__device__ __forceinline__ void mma_tile_core(
    uint32_t sQb, uint32_t sKb, int wm, int wn, int lane, float acc[2][8][4])
{
    // per-lane ldmatrix row/chunk mapping (bytes)
    const uint32_t a_off =
        sQb + (((wm * 32 + (lane & 15)) * 36 + (lane >> 4) * 4) << 2);
    const uint32_t b_off =
        sKb + (((wn * 64 + ((lane >> 4) << 3) + (lane & 7)) * 36
                + ((lane >> 3) & 1) * 4) << 2);
    #pragma unroll
    for (int k0w = 0; k0w < 32; k0w += 8) {   // 4 k16 steps (word offsets)
        uint32_t a[2][4], b[8][2];
        #pragma unroll
        for (int i = 0; i < 2; i++)
            ldsm_x4(a[i][0], a[i][1], a[i][2], a[i][3],
                    a_off + ((i * 16 * 36 + k0w) << 2));
        #pragma unroll
        for (int jp = 0; jp < 4; jp++)
            ldsm_x4(b[2 * jp][0], b[2 * jp][1], b[2 * jp + 1][0], b[2 * jp + 1][1],
                    b_off + ((jp * 16 * 36 + k0w) << 2));
        #pragma unroll
        for (int i = 0; i < 2; i++)
            #pragma unroll
            for (int j = 0; j < 8; j++)
                mma_bf16(acc[i][j], a[i][0], a[i][1], a[i][2], a[i][3],
                         b[j][0], b[j][1]);
    }
}

// ---------------------------------------------------------------------------
// Kernel 0: zero accumulated buffers
// ---------------------------------------------------------------------------
__global__ void zero_kernel() {
    int i = blockIdx.x * 256 + threadIdx.x;
    if (i < BH_ * L_) { g_ell[i] = 0.f; g_P[i] = 0.f; }
    if (i < B_ * NH_ * DM_) g_z[i] = 0.f;
    if (i < B_ * DM_) g_res[i] = 0.f;
}

// ---------------------------------------------------------------------------
// Kernel 1: Q/K projection via bf16 mma. C[16384,1024] = x @ [w_q;w_k]^T
// 128x128 tile; depth 512 staged as 8 chunks of 64 (bf16-converted in smem).
// ---------------------------------------------------------------------------
__global__ __launch_bounds__(256) void proj_kernel(
    const float* __restrict__ x,
    const float* __restrict__ wq,
    const float* __restrict__ wk)
{
    __shared__ uint32_t sA[128 * 36];
    __shared__ uint32_t sB[128 * 36];
    const int t = threadIdx.x;
    const int m0 = blockIdx.y << 7;
    const int n0 = blockIdx.x << 7;
    const int wid = t >> 5, lane = t & 31;
    const int wm = wid >> 1, wn = wid & 1;
    const int g = lane >> 2, tq = lane & 3;
    const uint32_t sAb = smem_u32(sA), sBb = smem_u32(sB);

    float acc[2][8][4] = {};

    for (int kc = 0; kc < 8; kc++) {
        #pragma unroll
        for (int f = t; f < 2048; f += 256) {
            int row = f >> 4, q4 = f & 15;      // 16 float4 per 64-col row
            float4 av = *(const float4*)(
                x + (size_t)(m0 + row) * DM_ + kc * 64 + q4 * 4);
            sA[row * 36 + q4 * 2]     = pack_bf162(av.x, av.y);
            sA[row * 36 + q4 * 2 + 1] = pack_bf162(av.z, av.w);
            int n = n0 + row;
            const float* src = (n < 512) ? (wq + (size_t)n * DM_)
                                         : (wk + (size_t)(n - 512) * DM_);
            float4 bv = *(const float4*)(src + kc * 64 + q4 * 4);
            sB[row * 36 + q4 * 2]     = pack_bf162(bv.x, bv.y);
            sB[row * 36 + q4 * 2 + 1] = pack_bf162(bv.z, bv.w);
        }
        __syncthreads();
        mma_tile_core(sAb, sBb, wm, wn, lane, acc);
        __syncthreads();
    }

    // Epilogue: bf16x2 stores into g_Qh (scaled) / g_Kh, [b][h][l][d]
    #pragma unroll
    for (int i = 0; i < 2; i++) {
        #pragma unroll
        for (int rr = 0; rr < 2; rr++) {
            int r = m0 + wm * 32 + i * 16 + g + rr * 8;
            int bidx = r >> 11, l = r & 2047;
            #pragma unroll
            for (int j = 0; j < 8; j++) {
                int n = n0 + wn * 64 + j * 8 + 2 * tq;
                float v0 = acc[i][j][rr * 2 + 0];
                float v1 = acc[i][j][rr * 2 + 1];
                if (n < 512) {
                    int h = n >> 6, d = n & 63;
                    *(uint32_t*)&g_Qh[(((size_t)(bidx << 3) + h) * L_ + l) * DK_ + d] =
                        pack_bf162(v0 * QSCALE, v1 * QSCALE);
                } else {
                    int n2 = n - 512;
                    int h = n2 >> 6, d = n2 & 63;
                    *(uint32_t*)&g_Kh[(((size_t)(bidx << 3) + h) * L_ + l) * DK_ + d] =
                        pack_bf162(v0, v1);
                }
            }
        }
    }
}

// ---------------------------------------------------------------------------
// Attention tile loads (bf16 Q/K, rows of 32 words, stride 36)
// ---------------------------------------------------------------------------
__device__ __forceinline__ void attn_load_tiles(
    uint32_t* sQ, uint32_t* sK, int bh, int q0, int k0b, int t)
{
    const uint32_t* qsrc =
        (const uint32_t*)(g_Qh + (size_t)bh * L_ * DK_ + (size_t)q0 * DK_);
    const uint32_t* ksrc =
        (const uint32_t*)(g_Kh + (size_t)bh * L_ * DK_ + (size_t)k0b * DK_);
    #pragma unroll
    for (int f = t; f < 1024; f += 256) {
        int row = f >> 3, w4 = (f & 7) << 2;   // 32 words/row, 8 uint4
        *(uint4*)&sQ[row * 36 + w4] = *(const uint4*)(qsrc + row * 32 + w4);
        *(uint4*)&sK[row * 36 + w4] = *(const uint4*)(ksrc + row * 32 + w4);
    }
}

// ---------------------------------------------------------------------------
// Kernel 2a: pass 1 — row sums of exp2(S) into g_ell (atomics).
// ---------------------------------------------------------------------------
__global__ __launch_bounds__(256) void attn_rowsum_kernel()
{
    __shared__ uint32_t sQ[128 * 36];
    __shared__ uint32_t sK[128 * 36];
    const int t = threadIdx.x;
    const int bh = blockIdx.z;
    const int q0 = blockIdx.y << 7;
    const int k0b = blockIdx.x << 7;
    const int wid = t >> 5, lane = t & 31;
    const int wm = wid >> 1, wn = wid & 1;
    const int g = lane >> 2;

    attn_load_tiles(sQ, sK, bh, q0, k0b, t);
    __syncthreads();

    float acc[2][8][4] = {};
    mma_tile_core(smem_u32(sQ), smem_u32(sK), wm, wn, lane, acc);

    #pragma unroll
    for (int i = 0; i < 2; i++) {
        int r0 = q0 + wm * 32 + i * 16 + g;
        int r1 = r0 + 8;
        float s0 = 0.f, s1 = 0.f;
        #pragma unroll
        for (int j = 0; j < 8; j++) {
            s0 += fast_exp2(acc[i][j][0]) + fast_exp2(acc[i][j][1]);
            s1 += fast_exp2(acc[i][j][2]) + fast_exp2(acc[i][j][3]);
        }
        s0 += __shfl_xor_sync(0xffffffffu, s0, 1);
        s0 += __shfl_xor_sync(0xffffffffu, s0, 2);
        s1 += __shfl_xor_sync(0xffffffffu, s1, 1);
        s1 += __shfl_xor_sync(0xffffffffu, s1, 2);
        if ((lane & 3) == 0) {
            atomicAdd(&g_ell[bh * L_ + r0], s0);
            atomicAdd(&g_ell[bh * L_ + r1], s1);
        }
    }
}

// ---------------------------------------------------------------------------
// Kernel 2b: pass 2 — recompute S, scale rows by 1/ell, column sums -> g_P.
// ---------------------------------------------------------------------------
__global__ __launch_bounds__(256) void attn_colsum_kernel()
{
    __shared__ uint32_t sQ[128 * 36];
    __shared__ uint32_t sK[128 * 36];
    __shared__ float colsum[128];
    const int t = threadIdx.x;
    const int bh = blockIdx.z;
    const int q0 = blockIdx.y << 7;
    const int k0b = blockIdx.x << 7;
    const int wid = t >> 5, lane = t & 31;
    const int wm = wid >> 1, wn = wid & 1;
    const int g = lane >> 2, tq = lane & 3;

    attn_load_tiles(sQ, sK, bh, q0, k0b, t);
    if (t < 128) colsum[t] = 0.f;
    __syncthreads();

    float acc[2][8][4] = {};
    mma_tile_core(smem_u32(sQ), smem_u32(sK), wm, wn, lane, acc);

    // per-row 1/ell (4 distinct rows per thread)
    float inv[2][2];
    #pragma unroll
    for (int i = 0; i < 2; i++) {
        int r0 = q0 + wm * 32 + i * 16 + g;
        inv[i][0] = 1.0f / g_ell[bh * L_ + r0];
        inv[i][1] = 1.0f / g_ell[bh * L_ + r0 + 8];
    }

    // per-thread partial column sums (16 cols: j*8 + 2tq + {0,1})
    float cs[16];
    #pragma unroll
    for (int c = 0; c < 16; c++) cs[c] = 0.f;
    #pragma unroll
    for (int i = 0; i < 2; i++) {
        #pragma unroll
        for (int j = 0; j < 8; j++) {
            float e0 = fast_exp2(acc[i][j][0]);
            float e1 = fast_exp2(acc[i][j][1]);
            float e2 = fast_exp2(acc[i][j][2]);
            float e3 = fast_exp2(acc[i][j][3]);
            cs[2 * j]     += e0 * inv[i][0] + e2 * inv[i][1];
            cs[2 * j + 1] += e1 * inv[i][0] + e3 * inv[i][1];
        }
    }
    // reduce over the 8 g-lanes (lane bits 2,3,4)
    #pragma unroll
    for (int off = 4; off <= 16; off <<= 1)
        #pragma unroll
        for (int c = 0; c < 16; c++)
            cs[c] += __shfl_xor_sync(0xffffffffu, cs[c], off);

    if (lane < 4) {   // g == 0, tq == lane
        #pragma unroll
        for (int j = 0; j < 8; j++) {
            atomicAdd(&colsum[wn * 64 + j * 8 + 2 * tq],     cs[2 * j]);
            atomicAdd(&colsum[wn * 64 + j * 8 + 2 * tq + 1], cs[2 * j + 1]);
        }
    }
    __syncthreads();
    if (t < 128)
        atomicAdd(&g_P[bh * L_ + k0b + t], colsum[t] * (1.0f / (float)L_));
}

// ---------------------------------------------------------------------------
// Kernel 4: z[b,h,m] = sum_l P[b,h,l]*x[b,l,m]; residual sums
// ---------------------------------------------------------------------------
__global__ __launch_bounds__(512) void zres_kernel(const float* __restrict__ x)
{
    __shared__ float Ps[8][128];
    const int lc = blockIdx.x;
    const int b  = blockIdx.y;
    const int t  = threadIdx.x;
    for (int i = t; i < 1024; i += 512) {
        int h = i >> 7, l = i & 127;
        Ps[h][l] = g_P[((b << 3) + h) * L_ + (lc << 7) + l];
    }
    __syncthreads();

    float zacc[8] = {};
    float racc = 0.f;
    const float* xb = x + ((size_t)b * L_ + (size_t)(lc << 7)) * DM_ + t;
    #pragma unroll 4
    for (int ll = 0; ll < 128; ll++) {
        float xv = xb[(size_t)ll * DM_];
        racc += xv;
        #pragma unroll
        for (int h = 0; h < 8; h++)
            zacc[h] += Ps[h][ll] * xv;
    }
    atomicAdd(&g_res[(b << 9) + t], racc);
    #pragma unroll
    for (int h = 0; h < 8; h++)
        atomicAdd(&g_z[(((b << 3) + h) << 9) + t], zacc[h]);
}

// ---------------------------------------------------------------------------
// Kernel 5: attn_ret, out = z@w_v^T/L, flat@w_fc^T + residual, layernorm
// ---------------------------------------------------------------------------
__global__ __launch_bounds__(512) void finalize_kernel(
    const float* __restrict__ w_v,
    const float* __restrict__ w_fc,
    const float* __restrict__ gamma,
    const float* __restrict__ beta,
    float* __restrict__ out)
{
    __shared__ float zsh[4096];
    __shared__ float flat[512];
    __shared__ float rs[16], rq[16];
    __shared__ float stats[2];
    const int b = blockIdx.x;
    const int t = threadIdx.x;

    for (int i = t; i < 4096; i += 512)
        zsh[i] = g_z[(size_t)b * 4096 + i];

    for (int k = t; k < L_; k += 512) {
        float s = 0.f;
        #pragma unroll
        for (int h = 0; h < 8; h++)
            s += g_P[((b << 3) + h) * L_ + k];
        out[4096 + b * L_ + k] = s * 0.125f;
    }
    __syncthreads();

    {
        const int h = t >> 6, dv = t & 63;
        const float4* wv4 = (const float4*)(w_v + (size_t)((h << 6) + dv) * DM_);
        const float4* z4  = (const float4*)(zsh + (h << 9));
        float ov = 0.f;
        #pragma unroll 8
        for (int m = 0; m < DM_ / 4; m++) {
            float4 a = z4[m], w = wv4[m];
            ov += a.x * w.x + a.y * w.y + a.z * w.z + a.w * w.w;
        }
        flat[(dv << 3) + h] = ov * (1.0f / (float)L_);
    }
    __syncthreads();

    float acc = g_res[(b << 9) + t] * (1.0f / (float)L_);
    {
        const float4* wf4 = (const float4*)(w_fc + (size_t)t * DM_);
        const float4* f4  = (const float4*)flat;
        #pragma unroll 8
        for (int m = 0; m < DM_ / 4; m++) {
            float4 f = f4[m], w = wf4[m];
            acc += f.x * w.x + f.y * w.y + f.z * w.z + f.w * w.w;
        }
    }

    float s1 = acc, s2 = acc * acc;
    #pragma unroll
    for (int off = 16; off; off >>= 1) {
        s1 += __shfl_xor_sync(0xffffffffu, s1, off);
        s2 += __shfl_xor_sync(0xffffffffu, s2, off);
    }
    if ((t & 31) == 0) { rs[t >> 5] = s1; rq[t >> 5] = s2; }
    __syncthreads();
    if (t == 0) {
        float S = 0.f, Q2 = 0.f;
        #pragma unroll
        for (int i = 0; i < 16; i++) { S += rs[i]; Q2 += rq[i]; }
        float mu  = S * (1.0f / 512.0f);
        float var = Q2 * (1.0f / 512.0f) - mu * mu;
        stats[0] = mu;
        stats[1] = rsqrtf(var + 1e-6f);
    }
    __syncthreads();
    out[(b << 9) + t] = (acc - stats[0]) * stats[1] * gamma[t] + beta[t];
}

// ---------------------------------------------------------------------------
extern "C" void kernel_launch(void* const* d_in, const int* in_sizes, int n_in,
                              void* d_out, int out_size)
{
    (void)in_sizes; (void)n_in; (void)out_size;
    const float* x     = (const float*)d_in[0];
    const float* w_q   = (const float*)d_in[1];
    const float* w_k   = (const float*)d_in[2];
    const float* w_v   = (const float*)d_in[3];
    const float* w_fc  = (const float*)d_in[4];
    const float* gamma = (const float*)d_in[5];
    const float* beta  = (const float*)d_in[6];
    float* out = (float*)d_out;

    zero_kernel<<<512, 256>>>();
    proj_kernel<<<dim3(8, 128), 256>>>(x, w_q, w_k);
    attn_rowsum_kernel<<<dim3(16, 16, 64), 256>>>();
    attn_colsum_kernel<<<dim3(16, 16, 64), 256>>>();
    zres_kernel<<<dim3(16, 8), 512>>>(x);
    finalize_kernel<<<8, 512>>>(w_v, w_fc, gamma, beta, out);
}

// round 10
// speedup vs baseline: 3.1495x; 1.1715x over previous
#include <cuda_runtime.h>
#include <cuda_bf16.h>
#include <cstdint>

// Problem constants
#define B_   8
#define L_   2048
#define DM_  512
#define NH_  8
#define DK_  64
#define BH_  (B_*NH_)            // 64
// Q pre-scale: (1/sqrt(DK)) * log2(e), so epilogue is ex2.approx
#define QSCALE 0.18033688011112043f

// Scratch (device globals; allocation-free kernel_launch)
__device__ __nv_bfloat16 g_Qh[BH_ * L_ * DK_];   // bf16, pre-scaled by QSCALE
__device__ __nv_bfloat16 g_Kh[BH_ * L_ * DK_];   // bf16
__device__ float g_ell[BH_ * L_];                // row sums of exp2(S)
__device__ float g_P[BH_ * L_];                  // pooled = colmean of softmax
__device__ float g_z[B_ * NH_ * DM_];            // z[b,h,m] = sum_k P*x
__device__ float g_res[B_ * DM_];                // sum over L of x (residual*L)

// ---------------------------------------------------------------------------
// Helpers
// ---------------------------------------------------------------------------
__device__ __forceinline__ float fast_exp2(float x) {
    float r;
    asm("ex2.approx.f32 %0, %1;" : "=f"(r) : "f"(x));
    return r;
}
__device__ __forceinline__ uint32_t pack_bf162(float lo, float hi) {
    uint32_t r;
    asm("cvt.rn.bf16x2.f32 %0, %1, %2;" : "=r"(r) : "f"(hi), "f"(lo));
    return r;
}
__device__ __forceinline__ void mma_bf16(float c[4],
    uint32_t a0, uint32_t a1, uint32_t a2, uint32_t a3,
    uint32_t b0, uint32_t b1)
{
    asm volatile(
        "mma.sync.aligned.m16n8k16.row.col.f32.bf16.bf16.f32 "
        "{%0,%1,%2,%3}, {%4,%5,%6,%7}, {%8,%9}, {%0,%1,%2,%3};\n"
        : "+f"(c[0]), "+f"(c[1]), "+f"(c[2]), "+f"(c[3])
        : "r"(a0), "r"(a1), "r"(a2), "r"(a3), "r"(b0), "r"(b1));
}
__device__ __forceinline__ void ldsm_x4(uint32_t& r0, uint32_t& r1,
                                        uint32_t& r2, uint32_t& r3,
                                        uint32_t addr)
{
    asm volatile("ldmatrix.sync.aligned.m8n8.x4.shared.b16 {%0,%1,%2,%3}, [%4];"
                 : "=r"(r0), "=r"(r1), "=r"(r2), "=r"(r3) : "r"(addr));
}
__device__ __forceinline__ uint32_t smem_u32(const void* p) {
    return (uint32_t)__cvta_generic_to_shared(p);
}

// ---------------------------------------------------------------------------
// Shared bf16 MMA tile core: 128x128 output tile per 256-thread block,
// 8 warps with 32x64 warp tiles, depth 64 (4 k16 steps). ldmatrix.x4
// fragments; smem rows 32 words, stride 36 (conflict-free).
// ---------------------------------------------------------------------------
__device__ __forceinline__ void mma_tile_core(
    uint32_t sQb, uint32_t sKb, int wm, int wn, int lane, float acc[2][8][4])
{
    const uint32_t a_off =
        sQb + (((wm * 32 + (lane & 15)) * 36 + (lane >> 4) * 4) << 2);
    const uint32_t b_off =
        sKb + (((wn * 64 + ((lane >> 4) << 3) + (lane & 7)) * 36
                + ((lane >> 3) & 1) * 4) << 2);
    #pragma unroll
    for (int k0w = 0; k0w < 32; k0w += 8) {
        uint32_t a[2][4], b[8][2];
        #pragma unroll
        for (int i = 0; i < 2; i++)
            ldsm_x4(a[i][0], a[i][1], a[i][2], a[i][3],
                    a_off + ((i * 16 * 36 + k0w) << 2));
        #pragma unroll
        for (int jp = 0; jp < 4; jp++)
            ldsm_x4(b[2 * jp][0], b[2 * jp][1], b[2 * jp + 1][0], b[2 * jp + 1][1],
                    b_off + ((jp * 16 * 36 + k0w) << 2));
        #pragma unroll
        for (int i = 0; i < 2; i++)
            #pragma unroll
            for (int j = 0; j < 8; j++)
                mma_bf16(acc[i][j], a[i][0], a[i][1], a[i][2], a[i][3],
                         b[j][0], b[j][1]);
    }
}

// ---------------------------------------------------------------------------
// Kernel 0: zero accumulated buffers (only z/res are atomically accumulated)
// ---------------------------------------------------------------------------
__global__ void zero_kernel() {
    int i = blockIdx.x * 256 + threadIdx.x;
    if (i < B_ * NH_ * DM_) g_z[i] = 0.f;
    if (i < B_ * DM_) g_res[i] = 0.f;
}

// ---------------------------------------------------------------------------
// Kernel 1: Q/K projection via bf16 mma. C[16384,1024] = x @ [w_q;w_k]^T
// ---------------------------------------------------------------------------
__global__ __launch_bounds__(256) void proj_kernel(
    const float* __restrict__ x,
    const float* __restrict__ wq,
    const float* __restrict__ wk)
{
    __shared__ uint32_t sA[128 * 36];
    __shared__ uint32_t sB[128 * 36];
    const int t = threadIdx.x;
    const int m0 = blockIdx.y << 7;
    const int n0 = blockIdx.x << 7;
    const int wid = t >> 5, lane = t & 31;
    const int wm = wid >> 1, wn = wid & 1;
    const int g = lane >> 2, tq = lane & 3;
    const uint32_t sAb = smem_u32(sA), sBb = smem_u32(sB);

    float acc[2][8][4] = {};

    #pragma unroll 1
    for (int kc = 0; kc < 8; kc++) {
        #pragma unroll
        for (int f = t; f < 2048; f += 256) {
            int row = f >> 4, q4 = f & 15;
            float4 av = *(const float4*)(
                x + (size_t)(m0 + row) * DM_ + kc * 64 + q4 * 4);
            sA[row * 36 + q4 * 2]     = pack_bf162(av.x, av.y);
            sA[row * 36 + q4 * 2 + 1] = pack_bf162(av.z, av.w);
            int n = n0 + row;
            const float* src = (n < 512) ? (wq + (size_t)n * DM_)
                                         : (wk + (size_t)(n - 512) * DM_);
            float4 bv = *(const float4*)(src + kc * 64 + q4 * 4);
            sB[row * 36 + q4 * 2]     = pack_bf162(bv.x, bv.y);
            sB[row * 36 + q4 * 2 + 1] = pack_bf162(bv.z, bv.w);
        }
        __syncthreads();
        mma_tile_core(sAb, sBb, wm, wn, lane, acc);
        __syncthreads();
    }

    #pragma unroll
    for (int i = 0; i < 2; i++) {
        #pragma unroll
        for (int rr = 0; rr < 2; rr++) {
            int r = m0 + wm * 32 + i * 16 + g + rr * 8;
            int bidx = r >> 11, l = r & 2047;
            #pragma unroll
            for (int j = 0; j < 8; j++) {
                int n = n0 + wn * 64 + j * 8 + 2 * tq;
                float v0 = acc[i][j][rr * 2 + 0];
                float v1 = acc[i][j][rr * 2 + 1];
                if (n < 512) {
                    int h = n >> 6, d = n & 63;
                    *(uint32_t*)&g_Qh[(((size_t)(bidx << 3) + h) * L_ + l) * DK_ + d] =
                        pack_bf162(v0 * QSCALE, v1 * QSCALE);
                } else {
                    int n2 = n - 512;
                    int h = n2 >> 6, d = n2 & 63;
                    *(uint32_t*)&g_Kh[(((size_t)(bidx << 3) + h) * L_ + l) * DK_ + d] =
                        pack_bf162(v0, v1);
                }
            }
        }
    }
}

// ---------------------------------------------------------------------------
// Kernel 2a: q-strip persistent row sums. Block = (q-strip, bh).
// Q resident in smem; 16 K-tiles streamed with register prefetch.
// Row sums accumulate in regs across tiles; one direct store (no atomics).
// ---------------------------------------------------------------------------
__global__ __launch_bounds__(256) void attn_rowsum_kernel()
{
    __shared__ uint32_t sQ[128 * 36];
    __shared__ uint32_t sK[128 * 36];
    const int t = threadIdx.x;
    const int q0 = blockIdx.x << 7;
    const int bh = blockIdx.y;
    const int wid = t >> 5, lane = t & 31;
    const int wm = wid >> 1, wn = wid & 1;
    const int g = lane >> 2;
    const int row = t >> 3, w4 = (t & 7) << 2;   // this thread's quad slot

    const uint32_t* qsrc =
        (const uint32_t*)(g_Qh + (size_t)bh * L_ * DK_ + (size_t)q0 * DK_);
    const uint32_t* kbase = (const uint32_t*)(g_Kh + (size_t)bh * L_ * DK_);
    #pragma unroll
    for (int f = t; f < 1024; f += 256) {
        int rr = f >> 3, ww = (f & 7) << 2;
        *(uint4*)&sQ[rr * 36 + ww] = *(const uint4*)(qsrc + rr * 32 + ww);
    }

    // prefetch K tile 0 (4 uint4 per thread; rows row+32p)
    uint4 pre[4];
    #pragma unroll
    for (int p = 0; p < 4; p++)
        pre[p] = *(const uint4*)(kbase + (row + 32 * p) * 32 + w4);

    float rs[2][2] = {};
    const uint32_t sQb = smem_u32(sQ), sKb = smem_u32(sK);

    #pragma unroll 1
    for (int kt = 0; kt < 16; kt++) {
        #pragma unroll
        for (int p = 0; p < 4; p++)
            *(uint4*)&sK[(row + 32 * p) * 36 + w4] = pre[p];
        __syncthreads();
        if (kt < 15) {
            const uint32_t* nxt = kbase + (kt + 1) * 4096;
            #pragma unroll
            for (int p = 0; p < 4; p++)
                pre[p] = *(const uint4*)(nxt + (row + 32 * p) * 32 + w4);
        }
        float acc[2][8][4] = {};
        mma_tile_core(sQb, sKb, wm, wn, lane, acc);
        #pragma unroll
        for (int i = 0; i < 2; i++)
            #pragma unroll
            for (int j = 0; j < 8; j++) {
                rs[i][0] += fast_exp2(acc[i][j][0]) + fast_exp2(acc[i][j][1]);
                rs[i][1] += fast_exp2(acc[i][j][2]) + fast_exp2(acc[i][j][3]);
            }
        __syncthreads();
    }

    // reduce over tq lanes (1,2) and wn warps (same rows; smem combine)
    __shared__ float rsum[2][128];   // [wn][row in strip]
    #pragma unroll
    for (int i = 0; i < 2; i++) {
        #pragma unroll
        for (int rr = 0; rr < 2; rr++) {
            float s = rs[i][rr];
            s += __shfl_xor_sync(0xffffffffu, s, 1);
            s += __shfl_xor_sync(0xffffffffu, s, 2);
            if ((lane & 3) == 0)
                rsum[wn][wm * 32 + i * 16 + rr * 8 + g] = s;
        }
    }
    __syncthreads();
    if (t < 128)
        g_ell[bh * L_ + q0 + t] = rsum[0][t] + rsum[1][t];
}

// ---------------------------------------------------------------------------
// Kernel 2b: k-strip persistent column sums. Block = (k-strip, bh).
// K resident; 16 Q-tiles streamed; cs[16] accumulates across tiles;
// one smem combine + direct store to g_P (no global atomics).
// ---------------------------------------------------------------------------
__global__ __launch_bounds__(256) void attn_colsum_kernel()
{
    __shared__ uint32_t sQ[128 * 36];
    __shared__ uint32_t sK[128 * 36];
    __shared__ float colsum[128];
    const int t = threadIdx.x;
    const int k0b = blockIdx.x << 7;
    const int bh = blockIdx.y;
    const int wid = t >> 5, lane = t & 31;
    const int wm = wid >> 1, wn = wid & 1;
    const int g = lane >> 2, tq = lane & 3;
    const int row = t >> 3, w4 = (t & 7) << 2;

    const uint32_t* ksrc =
        (const uint32_t*)(g_Kh + (size_t)bh * L_ * DK_ + (size_t)k0b * DK_);
    const uint32_t* qbase = (const uint32_t*)(g_Qh + (size_t)bh * L_ * DK_);
    #pragma unroll
    for (int f = t; f < 1024; f += 256) {
        int rr = f >> 3, ww = (f & 7) << 2;
        *(uint4*)&sK[rr * 36 + ww] = *(const uint4*)(ksrc + rr * 32 + ww);
    }
    if (t < 128) colsum[t] = 0.f;

    uint4 pre[4];
    #pragma unroll
    for (int p = 0; p < 4; p++)
        pre[p] = *(const uint4*)(qbase + (row + 32 * p) * 32 + w4);

    float cs[16];
    #pragma unroll
    for (int c = 0; c < 16; c++) cs[c] = 0.f;
    const uint32_t sQb = smem_u32(sQ), sKb = smem_u32(sK);
    const float* ellb = g_ell + bh * L_;

    #pragma unroll 1
    for (int qt = 0; qt < 16; qt++) {
        #pragma unroll
        for (int p = 0; p < 4; p++)
            *(uint4*)&sQ[(row + 32 * p) * 36 + w4] = pre[p];
        __syncthreads();
        if (qt < 15) {
            const uint32_t* nxt = qbase + (qt + 1) * 4096;
            #pragma unroll
            for (int p = 0; p < 4; p++)
                pre[p] = *(const uint4*)(nxt + (row + 32 * p) * 32 + w4);
        }
        float acc[2][8][4] = {};
        mma_tile_core(sQb, sKb, wm, wn, lane, acc);

        int r0 = qt * 128 + wm * 32 + g;
        float inv00 = 1.0f / ellb[r0];
        float inv01 = 1.0f / ellb[r0 + 8];
        float inv10 = 1.0f / ellb[r0 + 16];
        float inv11 = 1.0f / ellb[r0 + 24];
        #pragma unroll
        for (int j = 0; j < 8; j++) {
            cs[2 * j]     += fast_exp2(acc[0][j][0]) * inv00
                           + fast_exp2(acc[0][j][2]) * inv01
                           + fast_exp2(acc[1][j][0]) * inv10
                           + fast_exp2(acc[1][j][2]) * inv11;
            cs[2 * j + 1] += fast_exp2(acc[0][j][1]) * inv00
                           + fast_exp2(acc[0][j][3]) * inv01
                           + fast_exp2(acc[1][j][1]) * inv10
                           + fast_exp2(acc[1][j][3]) * inv11;
        }
        __syncthreads();
    }

    // reduce over the 8 g-lanes (lane bits 2,3,4)
    #pragma unroll
    for (int off = 4; off <= 16; off <<= 1)
        #pragma unroll
        for (int c = 0; c < 16; c++)
            cs[c] += __shfl_xor_sync(0xffffffffu, cs[c], off);

    if (lane < 4) {   // g == 0, tq == lane; combine 4 wm-warps per wn half
        #pragma unroll
        for (int j = 0; j < 8; j++) {
            atomicAdd(&colsum[wn * 64 + j * 8 + 2 * tq],     cs[2 * j]);
            atomicAdd(&colsum[wn * 64 + j * 8 + 2 * tq + 1], cs[2 * j + 1]);
        }
    }
    __syncthreads();
    if (t < 128)
        g_P[bh * L_ + k0b + t] = colsum[t] * (1.0f / (float)L_);
}

// ---------------------------------------------------------------------------
// Kernel 4: z[b,h,m] = sum_l P[b,h,l]*x[b,l,m]; residual sums
// ---------------------------------------------------------------------------
__global__ __launch_bounds__(512) void zres_kernel(const float* __restrict__ x)
{
    __shared__ float Ps[8][128];
    const int lc = blockIdx.x;
    const int b  = blockIdx.y;
    const int t  = threadIdx.x;
    for (int i = t; i < 1024; i += 512) {
        int h = i >> 7, l = i & 127;
        Ps[h][l] = g_P[((b << 3) + h) * L_ + (lc << 7) + l];
    }
    __syncthreads();

    float zacc[8] = {};
    float racc = 0.f;
    const float* xb = x + ((size_t)b * L_ + (size_t)(lc << 7)) * DM_ + t;
    #pragma unroll 4
    for (int ll = 0; ll < 128; ll++) {
        float xv = xb[(size_t)ll * DM_];
        racc += xv;
        #pragma unroll
        for (int h = 0; h < 8; h++)
            zacc[h] += Ps[h][ll] * xv;
    }
    atomicAdd(&g_res[(b << 9) + t], racc);
    #pragma unroll
    for (int h = 0; h < 8; h++)
        atomicAdd(&g_z[(((b << 3) + h) << 9) + t], zacc[h]);
}

// ---------------------------------------------------------------------------
// Kernel 5: attn_ret, out = z@w_v^T/L, flat@w_fc^T + residual, layernorm
// ---------------------------------------------------------------------------
__global__ __launch_bounds__(512) void finalize_kernel(
    const float* __restrict__ w_v,
    const float* __restrict__ w_fc,
    const float* __restrict__ gamma,
    const float* __restrict__ beta,
    float* __restrict__ out)
{
    __shared__ float zsh[4096];
    __shared__ float flat[512];
    __shared__ float rs[16], rq[16];
    __shared__ float stats[2];
    const int b = blockIdx.x;
    const int t = threadIdx.x;

    for (int i = t; i < 4096; i += 512)
        zsh[i] = g_z[(size_t)b * 4096 + i];

    for (int k = t; k < L_; k += 512) {
        float s = 0.f;
        #pragma unroll
        for (int h = 0; h < 8; h++)
            s += g_P[((b << 3) + h) * L_ + k];
        out[4096 + b * L_ + k] = s * 0.125f;
    }
    __syncthreads();

    {
        const int h = t >> 6, dv = t & 63;
        const float4* wv4 = (const float4*)(w_v + (size_t)((h << 6) + dv) * DM_);
        const float4* z4  = (const float4*)(zsh + (h << 9));
        float ov = 0.f;
        #pragma unroll 8
        for (int m = 0; m < DM_ / 4; m++) {
            float4 a = z4[m], w = wv4[m];
            ov += a.x * w.x + a.y * w.y + a.z * w.z + a.w * w.w;
        }
        flat[(dv << 3) + h] = ov * (1.0f / (float)L_);
    }
    __syncthreads();

    float acc = g_res[(b << 9) + t] * (1.0f / (float)L_);
    {
        const float4* wf4 = (const float4*)(w_fc + (size_t)t * DM_);
        const float4* f4  = (const float4*)flat;
        #pragma unroll 8
        for (int m = 0; m < DM_ / 4; m++) {
            float4 f = f4[m], w = wf4[m];
            acc += f.x * w.x + f.y * w.y + f.z * w.z + f.w * w.w;
        }
    }

    float s1 = acc, s2 = acc * acc;
    #pragma unroll
    for (int off = 16; off; off >>= 1) {
        s1 += __shfl_xor_sync(0xffffffffu, s1, off);
        s2 += __shfl_xor_sync(0xffffffffu, s2, off);
    }
    if ((t & 31) == 0) { rs[t >> 5] = s1; rq[t >> 5] = s2; }
    __syncthreads();
    if (t == 0) {
        float S = 0.f, Q2 = 0.f;
        #pragma unroll
        for (int i = 0; i < 16; i++) { S += rs[i]; Q2 += rq[i]; }
        float mu  = S * (1.0f / 512.0f);
        float var = Q2 * (1.0f / 512.0f) - mu * mu;
        stats[0] = mu;
        stats[1] = rsqrtf(var + 1e-6f);
    }
    __syncthreads();
    out[(b << 9) + t] = (acc - stats[0]) * stats[1] * gamma[t] + beta[t];
}

// ---------------------------------------------------------------------------
extern "C" void kernel_launch(void* const* d_in, const int* in_sizes, int n_in,
                              void* d_out, int out_size)
{
    (void)in_sizes; (void)n_in; (void)out_size;
    const float* x     = (const float*)d_in[0];
    const float* w_q   = (const float*)d_in[1];
    const float* w_k   = (const float*)d_in[2];
    const float* w_v   = (const float*)d_in[3];
    const float* w_fc  = (const float*)d_in[4];
    const float* gamma = (const float*)d_in[5];
    const float* beta  = (const float*)d_in[6];
    float* out = (float*)d_out;

    zero_kernel<<<144, 256>>>();
    proj_kernel<<<dim3(8, 128), 256>>>(x, w_q, w_k);
    attn_rowsum_kernel<<<dim3(16, 64), 256>>>();
    attn_colsum_kernel<<<dim3(16, 64), 256>>>();
    zres_kernel<<<dim3(16, 8), 512>>>(x);
    finalize_kernel<<<8, 512>>>(w_v, w_fc, gamma, beta, out);
}

// round 11
// speedup vs baseline: 3.2233x; 1.0234x over previous
#include <cuda_runtime.h>
#include <cuda_bf16.h>
#include <cstdint>

// Problem constants
#define B_   8
#define L_   2048
#define DM_  512
#define NH_  8
#define DK_  64
#define BH_  (B_*NH_)            // 64
// Q pre-scale: (1/sqrt(DK)) * log2(e), so epilogue is ex2.approx
#define QSCALE 0.18033688011112043f

#define TILE_W 36                 // words per smem row
#define TILE_WORDS (128 * TILE_W) // 4608 words = 18432 B per tile

// Scratch (device globals; allocation-free kernel_launch)
__device__ __nv_bfloat16 g_Qh[BH_ * L_ * DK_];   // bf16, pre-scaled by QSCALE
__device__ __nv_bfloat16 g_Kh[BH_ * L_ * DK_];   // bf16
__device__ float g_ell[BH_ * L_];                // row sums of exp2(S)
__device__ float g_P[BH_ * L_];                  // pooled = colmean of softmax
__device__ float g_z[B_ * NH_ * DM_];            // z[b,h,m] = sum_k P*x
__device__ float g_res[B_ * DM_];                // sum over L of x (residual*L)

// ---------------------------------------------------------------------------
// Helpers
// ---------------------------------------------------------------------------
__device__ __forceinline__ float fast_exp2(float x) {
    float r;
    asm("ex2.approx.f32 %0, %1;" : "=f"(r) : "f"(x));
    return r;
}
__device__ __forceinline__ uint32_t pack_bf162(float lo, float hi) {
    uint32_t r;
    asm("cvt.rn.bf16x2.f32 %0, %1, %2;" : "=r"(r) : "f"(hi), "f"(lo));
    return r;
}
__device__ __forceinline__ void mma_bf16(float c[4],
    uint32_t a0, uint32_t a1, uint32_t a2, uint32_t a3,
    uint32_t b0, uint32_t b1)
{
    asm volatile(
        "mma.sync.aligned.m16n8k16.row.col.f32.bf16.bf16.f32 "
        "{%0,%1,%2,%3}, {%4,%5,%6,%7}, {%8,%9}, {%0,%1,%2,%3};\n"
        : "+f"(c[0]), "+f"(c[1]), "+f"(c[2]), "+f"(c[3])
        : "r"(a0), "r"(a1), "r"(a2), "r"(a3), "r"(b0), "r"(b1));
}
__device__ __forceinline__ void ldsm_x4(uint32_t& r0, uint32_t& r1,
                                        uint32_t& r2, uint32_t& r3,
                                        uint32_t addr)
{
    asm volatile("ldmatrix.sync.aligned.m8n8.x4.shared.b16 {%0,%1,%2,%3}, [%4];"
                 : "=r"(r0), "=r"(r1), "=r"(r2), "=r"(r3) : "r"(addr));
}
__device__ __forceinline__ uint32_t smem_u32(const void* p) {
    return (uint32_t)__cvta_generic_to_shared(p);
}
__device__ __forceinline__ void cp16(uint32_t dst, const void* src) {
    asm volatile("cp.async.cg.shared.global [%0], [%1], 16;\n"
                 :: "r"(dst), "l"(src));
}
__device__ __forceinline__ void cp_commit() {
    asm volatile("cp.async.commit_group;\n" ::: "memory");
}
__device__ __forceinline__ void cp_wait1() {
    asm volatile("cp.async.wait_group 1;\n" ::: "memory");
}
__device__ __forceinline__ void cp_wait0() {
    asm volatile("cp.async.wait_group 0;\n" ::: "memory");
}

// ---------------------------------------------------------------------------
// Shared bf16 MMA tile core: 128x128 output tile per 256-thread block,
// 8 warps with 32x64 warp tiles, depth 64 (4 k16 steps). ldmatrix.x4
// fragments; smem rows 32 words, stride 36 (conflict-free).
// ---------------------------------------------------------------------------
__device__ __forceinline__ void mma_tile_core(
    uint32_t sQb, uint32_t sKb, int wm, int wn, int lane, float acc[2][8][4])
{
    const uint32_t a_off =
        sQb + (((wm * 32 + (lane & 15)) * TILE_W + (lane >> 4) * 4) << 2);
    const uint32_t b_off =
        sKb + (((wn * 64 + ((lane >> 4) << 3) + (lane & 7)) * TILE_W
                + ((lane >> 3) & 1) * 4) << 2);
    #pragma unroll
    for (int k0w = 0; k0w < 32; k0w += 8) {
        uint32_t a[2][4], b[8][2];
        #pragma unroll
        for (int i = 0; i < 2; i++)
            ldsm_x4(a[i][0], a[i][1], a[i][2], a[i][3],
                    a_off + ((i * 16 * TILE_W + k0w) << 2));
        #pragma unroll
        for (int jp = 0; jp < 4; jp++)
            ldsm_x4(b[2 * jp][0], b[2 * jp][1], b[2 * jp + 1][0], b[2 * jp + 1][1],
                    b_off + ((jp * 16 * TILE_W + k0w) << 2));
        #pragma unroll
        for (int i = 0; i < 2; i++)
            #pragma unroll
            for (int j = 0; j < 8; j++)
                mma_bf16(acc[i][j], a[i][0], a[i][1], a[i][2], a[i][3],
                         b[j][0], b[j][1]);
    }
}

// Issue the 4 cp.async for this thread's share of one 128x64 bf16 tile.
__device__ __forceinline__ void tile_cp_async(
    uint32_t dstb, const uint32_t* src, int row, int w4)
{
    #pragma unroll
    for (int p = 0; p < 4; p++)
        cp16(dstb + (((row + 32 * p) * TILE_W + w4) << 2),
             src + (row + 32 * p) * 32 + w4);
    cp_commit();
}

// ---------------------------------------------------------------------------
// Kernel 0: zero accumulated buffers (only z/res are atomically accumulated)
// ---------------------------------------------------------------------------
__global__ void zero_kernel() {
    int i = blockIdx.x * 256 + threadIdx.x;
    if (i < B_ * NH_ * DM_) g_z[i] = 0.f;
    if (i < B_ * DM_) g_res[i] = 0.f;
}

// ---------------------------------------------------------------------------
// Kernel 1: Q/K projection via bf16 mma. C[16384,1024] = x @ [w_q;w_k]^T
// ---------------------------------------------------------------------------
__global__ __launch_bounds__(256) void proj_kernel(
    const float* __restrict__ x,
    const float* __restrict__ wq,
    const float* __restrict__ wk)
{
    __shared__ uint32_t sA[TILE_WORDS];
    __shared__ uint32_t sB[TILE_WORDS];
    const int t = threadIdx.x;
    const int m0 = blockIdx.y << 7;
    const int n0 = blockIdx.x << 7;
    const int wid = t >> 5, lane = t & 31;
    const int wm = wid >> 1, wn = wid & 1;
    const int g = lane >> 2, tq = lane & 3;
    const uint32_t sAb = smem_u32(sA), sBb = smem_u32(sB);

    float acc[2][8][4] = {};

    #pragma unroll 1
    for (int kc = 0; kc < 8; kc++) {
        #pragma unroll
        for (int f = t; f < 2048; f += 256) {
            int row = f >> 4, q4 = f & 15;
            float4 av = *(const float4*)(
                x + (size_t)(m0 + row) * DM_ + kc * 64 + q4 * 4);
            sA[row * TILE_W + q4 * 2]     = pack_bf162(av.x, av.y);
            sA[row * TILE_W + q4 * 2 + 1] = pack_bf162(av.z, av.w);
            int n = n0 + row;
            const float* src = (n < 512) ? (wq + (size_t)n * DM_)
                                         : (wk + (size_t)(n - 512) * DM_);
            float4 bv = *(const float4*)(src + kc * 64 + q4 * 4);
            sB[row * TILE_W + q4 * 2]     = pack_bf162(bv.x, bv.y);
            sB[row * TILE_W + q4 * 2 + 1] = pack_bf162(bv.z, bv.w);
        }
        __syncthreads();
        mma_tile_core(sAb, sBb, wm, wn, lane, acc);
        __syncthreads();
    }

    #pragma unroll
    for (int i = 0; i < 2; i++) {
        #pragma unroll
        for (int rr = 0; rr < 2; rr++) {
            int r = m0 + wm * 32 + i * 16 + g + rr * 8;
            int bidx = r >> 11, l = r & 2047;
            #pragma unroll
            for (int j = 0; j < 8; j++) {
                int n = n0 + wn * 64 + j * 8 + 2 * tq;
                float v0 = acc[i][j][rr * 2 + 0];
                float v1 = acc[i][j][rr * 2 + 1];
                if (n < 512) {
                    int h = n >> 6, d = n & 63;
                    *(uint32_t*)&g_Qh[(((size_t)(bidx << 3) + h) * L_ + l) * DK_ + d] =
                        pack_bf162(v0 * QSCALE, v1 * QSCALE);
                } else {
                    int n2 = n - 512;
                    int h = n2 >> 6, d = n2 & 63;
                    *(uint32_t*)&g_Kh[(((size_t)(bidx << 3) + h) * L_ + l) * DK_ + d] =
                        pack_bf162(v0, v1);
                }
            }
        }
    }
}

// ---------------------------------------------------------------------------
// Kernel 2a: q-strip persistent row sums, cp.async ping-pong on K tiles.
// dyn smem: [sQ | sK0 | sK1]
// ---------------------------------------------------------------------------
__global__ __launch_bounds__(256) void attn_rowsum_kernel()
{
    extern __shared__ uint32_t dyn[];
    uint32_t* sQ = dyn;
    uint32_t* sK0 = dyn + TILE_WORDS;
    __shared__ float rsum[2][128];
    const int t = threadIdx.x;
    const int q0 = blockIdx.x << 7;
    const int bh = blockIdx.y;
    const int wid = t >> 5, lane = t & 31;
    const int wm = wid >> 1, wn = wid & 1;
    const int g = lane >> 2;
    const int row = t >> 3, w4 = (t & 7) << 2;

    const uint32_t* qsrc =
        (const uint32_t*)(g_Qh + (size_t)bh * L_ * DK_ + (size_t)q0 * DK_);
    const uint32_t* kbase = (const uint32_t*)(g_Kh + (size_t)bh * L_ * DK_);
    #pragma unroll
    for (int f = t; f < 1024; f += 256) {
        int rr = f >> 3, ww = (f & 7) << 2;
        *(uint4*)&sQ[rr * TILE_W + ww] = *(const uint4*)(qsrc + rr * 32 + ww);
    }

    const uint32_t sQb = smem_u32(sQ);
    const uint32_t sKb[2] = { smem_u32(sK0), smem_u32(sK0 + TILE_WORDS) };

    tile_cp_async(sKb[0], kbase, row, w4);   // tile 0 in flight

    float rs[2][2] = {};

    #pragma unroll 1
    for (int kt = 0; kt < 16; kt++) {
        if (kt < 15) {
            tile_cp_async(sKb[(kt + 1) & 1], kbase + (kt + 1) * 4096, row, w4);
            cp_wait1();
        } else {
            cp_wait0();
        }
        __syncthreads();
        float acc[2][8][4] = {};
        mma_tile_core(sQb, sKb[kt & 1], wm, wn, lane, acc);
        #pragma unroll
        for (int i = 0; i < 2; i++)
            #pragma unroll
            for (int j = 0; j < 8; j++) {
                rs[i][0] += fast_exp2(acc[i][j][0]) + fast_exp2(acc[i][j][1]);
                rs[i][1] += fast_exp2(acc[i][j][2]) + fast_exp2(acc[i][j][3]);
            }
        __syncthreads();   // protect buffer reuse next iteration
    }

    #pragma unroll
    for (int i = 0; i < 2; i++) {
        #pragma unroll
        for (int rr = 0; rr < 2; rr++) {
            float s = rs[i][rr];
            s += __shfl_xor_sync(0xffffffffu, s, 1);
            s += __shfl_xor_sync(0xffffffffu, s, 2);
            if ((lane & 3) == 0)
                rsum[wn][wm * 32 + i * 16 + rr * 8 + g] = s;
        }
    }
    __syncthreads();
    if (t < 128)
        g_ell[bh * L_ + q0 + t] = rsum[0][t] + rsum[1][t];
}

// ---------------------------------------------------------------------------
// Kernel 2b: k-strip persistent column sums, cp.async ping-pong on Q tiles.
// dyn smem: [sK | sQ0 | sQ1]
// ---------------------------------------------------------------------------
__global__ __launch_bounds__(256) void attn_colsum_kernel()
{
    extern __shared__ uint32_t dyn[];
    uint32_t* sK = dyn;
    uint32_t* sQ0 = dyn + TILE_WORDS;
    __shared__ float colsum[128];
    const int t = threadIdx.x;
    const int k0b = blockIdx.x << 7;
    const int bh = blockIdx.y;
    const int wid = t >> 5, lane = t & 31;
    const int wm = wid >> 1, wn = wid & 1;
    const int g = lane >> 2, tq = lane & 3;
    const int row = t >> 3, w4 = (t & 7) << 2;

    const uint32_t* ksrc =
        (const uint32_t*)(g_Kh + (size_t)bh * L_ * DK_ + (size_t)k0b * DK_);
    const uint32_t* qbase = (const uint32_t*)(g_Qh + (size_t)bh * L_ * DK_);
    #pragma unroll
    for (int f = t; f < 1024; f += 256) {
        int rr = f >> 3, ww = (f & 7) << 2;
        *(uint4*)&sK[rr * TILE_W + ww] = *(const uint4*)(ksrc + rr * 32 + ww);
    }
    if (t < 128) colsum[t] = 0.f;

    const uint32_t sKb = smem_u32(sK);
    const uint32_t sQb[2] = { smem_u32(sQ0), smem_u32(sQ0 + TILE_WORDS) };

    tile_cp_async(sQb[0], qbase, row, w4);

    float cs[16];
    #pragma unroll
    for (int c = 0; c < 16; c++) cs[c] = 0.f;
    const float* ellb = g_ell + bh * L_;

    #pragma unroll 1
    for (int qt = 0; qt < 16; qt++) {
        if (qt < 15) {
            tile_cp_async(sQb[(qt + 1) & 1], qbase + (qt + 1) * 4096, row, w4);
            cp_wait1();
        } else {
            cp_wait0();
        }
        __syncthreads();
        float acc[2][8][4] = {};
        mma_tile_core(sQb[qt & 1], sKb, wm, wn, lane, acc);

        int r0 = qt * 128 + wm * 32 + g;
        float inv00 = 1.0f / ellb[r0];
        float inv01 = 1.0f / ellb[r0 + 8];
        float inv10 = 1.0f / ellb[r0 + 16];
        float inv11 = 1.0f / ellb[r0 + 24];
        #pragma unroll
        for (int j = 0; j < 8; j++) {
            cs[2 * j]     += fast_exp2(acc[0][j][0]) * inv00
                           + fast_exp2(acc[0][j][2]) * inv01
                           + fast_exp2(acc[1][j][0]) * inv10
                           + fast_exp2(acc[1][j][2]) * inv11;
            cs[2 * j + 1] += fast_exp2(acc[0][j][1]) * inv00
                           + fast_exp2(acc[0][j][3]) * inv01
                           + fast_exp2(acc[1][j][1]) * inv10
                           + fast_exp2(acc[1][j][3]) * inv11;
        }
        __syncthreads();   // protect buffer reuse next iteration
    }

    // reduce over the 8 g-lanes (lane bits 2,3,4)
    #pragma unroll
    for (int off = 4; off <= 16; off <<= 1)
        #pragma unroll
        for (int c = 0; c < 16; c++)
            cs[c] += __shfl_xor_sync(0xffffffffu, cs[c], off);

    if (lane < 4) {   // g == 0, tq == lane; combine 4 wm-warps per wn half
        #pragma unroll
        for (int j = 0; j < 8; j++) {
            atomicAdd(&colsum[wn * 64 + j * 8 + 2 * tq],     cs[2 * j]);
            atomicAdd(&colsum[wn * 64 + j * 8 + 2 * tq + 1], cs[2 * j + 1]);
        }
    }
    __syncthreads();
    if (t < 128)
        g_P[bh * L_ + k0b + t] = colsum[t] * (1.0f / (float)L_);
}

// ---------------------------------------------------------------------------
// Kernel 4: z[b,h,m] = sum_l P[b,h,l]*x[b,l,m]; residual sums
// ---------------------------------------------------------------------------
__global__ __launch_bounds__(512) void zres_kernel(const float* __restrict__ x)
{
    __shared__ float Ps[8][128];
    const int lc = blockIdx.x;
    const int b  = blockIdx.y;
    const int t  = threadIdx.x;
    for (int i = t; i < 1024; i += 512) {
        int h = i >> 7, l = i & 127;
        Ps[h][l] = g_P[((b << 3) + h) * L_ + (lc << 7) + l];
    }
    __syncthreads();

    float zacc[8] = {};
    float racc = 0.f;
    const float* xb = x + ((size_t)b * L_ + (size_t)(lc << 7)) * DM_ + t;
    #pragma unroll 4
    for (int ll = 0; ll < 128; ll++) {
        float xv = xb[(size_t)ll * DM_];
        racc += xv;
        #pragma unroll
        for (int h = 0; h < 8; h++)
            zacc[h] += Ps[h][ll] * xv;
    }
    atomicAdd(&g_res[(b << 9) + t], racc);
    #pragma unroll
    for (int h = 0; h < 8; h++)
        atomicAdd(&g_z[(((b << 3) + h) << 9) + t], zacc[h]);
}

// ---------------------------------------------------------------------------
// Kernel 5: attn_ret, out = z@w_v^T/L, flat@w_fc^T + residual, layernorm
// ---------------------------------------------------------------------------
__global__ __launch_bounds__(512) void finalize_kernel(
    const float* __restrict__ w_v,
    const float* __restrict__ w_fc,
    const float* __restrict__ gamma,
    const float* __restrict__ beta,
    float* __restrict__ out)
{
    __shared__ float zsh[4096];
    __shared__ float flat[512];
    __shared__ float rs[16], rq[16];
    __shared__ float stats[2];
    const int b = blockIdx.x;
    const int t = threadIdx.x;

    for (int i = t; i < 4096; i += 512)
        zsh[i] = g_z[(size_t)b * 4096 + i];

    for (int k = t; k < L_; k += 512) {
        float s = 0.f;
        #pragma unroll
        for (int h = 0; h < 8; h++)
            s += g_P[((b << 3) + h) * L_ + k];
        out[4096 + b * L_ + k] = s * 0.125f;
    }
    __syncthreads();

    {
        const int h = t >> 6, dv = t & 63;
        const float4* wv4 = (const float4*)(w_v + (size_t)((h << 6) + dv) * DM_);
        const float4* z4  = (const float4*)(zsh + (h << 9));
        float ov = 0.f;
        #pragma unroll 8
        for (int m = 0; m < DM_ / 4; m++) {
            float4 a = z4[m], w = wv4[m];
            ov += a.x * w.x + a.y * w.y + a.z * w.z + a.w * w.w;
        }
        flat[(dv << 3) + h] = ov * (1.0f / (float)L_);
    }
    __syncthreads();

    float acc = g_res[(b << 9) + t] * (1.0f / (float)L_);
    {
        const float4* wf4 = (const float4*)(w_fc + (size_t)t * DM_);
        const float4* f4  = (const float4*)flat;
        #pragma unroll 8
        for (int m = 0; m < DM_ / 4; m++) {
            float4 f = f4[m], w = wf4[m];
            acc += f.x * w.x + f.y * w.y + f.z * w.z + f.w * w.w;
        }
    }

    float s1 = acc, s2 = acc * acc;
    #pragma unroll
    for (int off = 16; off; off >>= 1) {
        s1 += __shfl_xor_sync(0xffffffffu, s1, off);
        s2 += __shfl_xor_sync(0xffffffffu, s2, off);
    }
    if ((t & 31) == 0) { rs[t >> 5] = s1; rq[t >> 5] = s2; }
    __syncthreads();
    if (t == 0) {
        float S = 0.f, Q2 = 0.f;
        #pragma unroll
        for (int i = 0; i < 16; i++) { S += rs[i]; Q2 += rq[i]; }
        float mu  = S * (1.0f / 512.0f);
        float var = Q2 * (1.0f / 512.0f) - mu * mu;
        stats[0] = mu;
        stats[1] = rsqrtf(var + 1e-6f);
    }
    __syncthreads();
    out[(b << 9) + t] = (acc - stats[0]) * stats[1] * gamma[t] + beta[t];
}

// ---------------------------------------------------------------------------
extern "C" void kernel_launch(void* const* d_in, const int* in_sizes, int n_in,
                              void* d_out, int out_size)
{
    (void)in_sizes; (void)n_in; (void)out_size;
    const float* x     = (const float*)d_in[0];
    const float* w_q   = (const float*)d_in[1];
    const float* w_k   = (const float*)d_in[2];
    const float* w_v   = (const float*)d_in[3];
    const float* w_fc  = (const float*)d_in[4];
    const float* gamma = (const float*)d_in[5];
    const float* beta  = (const float*)d_in[6];
    float* out = (float*)d_out;

    const int attn_smem = 3 * TILE_WORDS * 4;   // 55296 B
    cudaFuncSetAttribute(attn_rowsum_kernel,
                         cudaFuncAttributeMaxDynamicSharedMemorySize, attn_smem);
    cudaFuncSetAttribute(attn_colsum_kernel,
                         cudaFuncAttributeMaxDynamicSharedMemorySize, attn_smem);

    zero_kernel<<<144, 256>>>();
    proj_kernel<<<dim3(8, 128), 256>>>(x, w_q, w_k);
    attn_rowsum_kernel<<<dim3(16, 64), 256, attn_smem>>>();
    attn_colsum_kernel<<<dim3(16, 64), 256, attn_smem>>>();
    zres_kernel<<<dim3(16, 8), 512>>>(x);
    finalize_kernel<<<8, 512>>>(w_v, w_fc, gamma, beta, out);
}